// round 10
// baseline (speedup 1.0000x reference)
#include <cuda_runtime.h>
#include <cuda_fp16.h>

#define NN 102400
#define EE 1638400
#define ET (EE + NN)
#define GG 256
#define FULL 0xffffffffu

// ---------------- scratch (device globals; no allocation) ----------------
// Invariant: g_cnt and g_pool are ZERO at entry of every kernel_launch call.
__device__ __align__(16) __half g_h1h[NN * 128];
__device__ __align__(16) float  g_als1[NN * 4];
__device__ __align__(16) float  g_ald1[NN * 4];
__device__ __align__(16) __half g_act[NN * 128];
__device__ __align__(16) __half g_h2h[NN * 32];
__device__ __align__(16) float  g_als2[NN];
__device__ __align__(16) float  g_ald2[NN];
__device__ __align__(16) int    g_cnt[NN];
__device__ __align__(16) int    g_rowptr[NN + 4];
__device__ __align__(16) int    g_pos[NN];
__device__ __align__(16) int    g_csr[ET];
__device__ __align__(16) float  g_pool[GG * 32];
__device__ __align__(16) __half g_w1t[128 * 64];   // W1 transposed, fp16: [col][k]

__device__ __forceinline__ float eluf(float v) {
    return (v > 0.f) ? v : (__expf(v) - 1.f);
}
__device__ __forceinline__ float lrelu(float e) {
    return (e > 0.f) ? e : 0.2f * e;
}

#define FMA_F32X2(d, a, b, c) \
    asm("fma.rn.f32x2 %0, %1, %2, %3;" : "=l"(d) : "l"(a), "l"(b), "l"(c))

__device__ __forceinline__ unsigned long long packf2(float lo, float hi) {
    unsigned long long r;
    asm("mov.b64 %0, {%1, %2};" : "=l"(r) : "r"(__float_as_uint(lo)), "r"(__float_as_uint(hi)));
    return r;
}
__device__ __forceinline__ float2 unpackf2(unsigned long long v) {
    unsigned int lo, hi;
    asm("mov.b64 {%0, %1}, %2;" : "=r"(lo), "=r"(hi) : "l"(v));
    return make_float2(__uint_as_float(lo), __uint_as_float(hi));
}
__device__ __forceinline__ unsigned int packh2(float2 v) {
    __half2 h = __floats2half2_rn(v.x, v.y);
    return *(unsigned int*)&h;
}
__device__ __forceinline__ void mma16816(float* c,
                                         unsigned a0, unsigned a1, unsigned a2, unsigned a3,
                                         unsigned b0, unsigned b1) {
    asm volatile("mma.sync.aligned.m16n8k16.row.col.f32.f16.f16.f32 "
                 "{%0,%1,%2,%3}, {%4,%5,%6,%7}, {%8,%9}, {%0,%1,%2,%3};"
                 : "+f"(c[0]), "+f"(c[1]), "+f"(c[2]), "+f"(c[3])
                 : "r"(a0), "r"(a1), "r"(a2), "r"(a3), "r"(b0), "r"(b1));
}
__device__ __forceinline__ __half2 h2shfl_xor(__half2 v, int off) {
    unsigned u = __shfl_xor_sync(FULL, *(unsigned*)&v, off);
    return *(__half2*)&u;
}

// ---------------- launch 0: histogram of dst ----------------
__global__ void k_hist(const int* __restrict__ ei) {
    int t = blockIdx.x * blockDim.x + threadIdx.x;
    if (t < EE / 4) {
        int4 d4 = ((const int4*)(ei + EE))[t];
        atomicAdd(&g_cnt[d4.x], 1);
        atomicAdd(&g_cnt[d4.y], 1);
        atomicAdd(&g_cnt[d4.z], 1);
        atomicAdd(&g_cnt[d4.w], 1);
    }
}

// ---------------- launch 1: prefix scan (+self loops); resets g_cnt; builds W1T fp16 ----------------
__global__ void k_scan(const float* __restrict__ W1) {
    __shared__ int sp[1024];
    int t = threadIdx.x;
#pragma unroll
    for (int i = 0; i < 8; i++) {
        int idx = t * 8 + i;
        int n = idx >> 6, k = idx & 63;
        g_w1t[idx] = __float2half(W1[k * 128 + n]);
    }
    int4* cv = (int4*)(g_cnt + t * 100);
    int s = 0;
#pragma unroll
    for (int i = 0; i < 25; i++) {
        int4 c = cv[i];
        s += c.x + c.y + c.z + c.w + 4;
    }
    sp[t] = s;
    __syncthreads();
    for (int off = 1; off < 1024; off <<= 1) {
        int v = (t >= off) ? sp[t - off] : 0;
        __syncthreads();
        sp[t] += v;
        __syncthreads();
    }
    int run = t ? sp[t - 1] : 0;
    int4* rp = (int4*)(g_rowptr + t * 100);
    int4* pp = (int4*)(g_pos + t * 100);
    int4 zero = make_int4(0, 0, 0, 0);
#pragma unroll
    for (int i = 0; i < 25; i++) {
        int4 c = cv[i];
        int4 r;
        r.x = run; run += c.x + 1;
        r.y = run; run += c.y + 1;
        r.z = run; run += c.z + 1;
        r.w = run; run += c.w + 1;
        rp[i] = r;
        pp[i] = r;
        cv[i] = zero;
    }
    if (t == 1023) g_rowptr[NN] = ET;
}

// ---------------- launch 2: scatter CSR + tensor-core gemm1 ----------------
#define SCAT_BLOCKS 4000
__global__ void __launch_bounds__(128) k_scatter_gemm1(
        const int* __restrict__ ei,
        const float* __restrict__ x,
        const float* __restrict__ a_src1,
        const float* __restrict__ a_dst1) {
    if (blockIdx.x < SCAT_BLOCKS) {
        int t = blockIdx.x * 128 + threadIdx.x;
        const int Q = EE / 4;
        if (t < Q) {
            int4 s4 = ((const int4*)ei)[t];
            int4 d4 = ((const int4*)(ei + EE))[t];
            int p;
            p = atomicAdd(&g_pos[d4.x], 1); g_csr[p] = s4.x;
            p = atomicAdd(&g_pos[d4.y], 1); g_csr[p] = s4.y;
            p = atomicAdd(&g_pos[d4.z], 1); g_csr[p] = s4.z;
            p = atomicAdd(&g_pos[d4.w], 1); g_csr[p] = s4.w;
        } else {
            int n = t - Q;
            int p = atomicAdd(&g_pos[n], 1);
            g_csr[p] = n;
        }
        return;
    }
    int bid = blockIdx.x - SCAT_BLOCKS;
    int n0 = bid * 16;
    int w = threadIdx.x >> 5;
    int l = threadIdx.x & 31;
    int g = l >> 2, tg = l & 3;

    const float2* xg  = (const float2*)(x + (n0 + g) * 64);
    const float2* xg8 = (const float2*)(x + (n0 + g + 8) * 64);

    float acc[4][4];
#pragma unroll
    for (int t = 0; t < 4; t++)
#pragma unroll
        for (int i = 0; i < 4; i++) acc[t][i] = 0.f;

#pragma unroll
    for (int ks = 0; ks < 4; ks++) {
        unsigned a0 = packh2(xg [8 * ks + tg]);
        unsigned a1 = packh2(xg8[8 * ks + tg]);
        unsigned a2 = packh2(xg [8 * ks + tg + 4]);
        unsigned a3 = packh2(xg8[8 * ks + tg + 4]);
#pragma unroll
        for (int t = 0; t < 4; t++) {
            int col = 32 * w + 8 * t + g;
            unsigned b0 = *(const unsigned*)&g_w1t[col * 64 + 16 * ks + 2 * tg];
            unsigned b1 = *(const unsigned*)&g_w1t[col * 64 + 16 * ks + 2 * tg + 8];
            mma16816(acc[t], a0, a1, a2, a3, b0, b1);
        }
    }

    float psg = 0.f, psg8 = 0.f, pdg = 0.f, pdg8 = 0.f;
#pragma unroll
    for (int t = 0; t < 4; t++) {
        int c0 = 32 * w + 8 * t + 2 * tg;
        __half2 h01 = __floats2half2_rn(acc[t][0], acc[t][1]);
        __half2 h23 = __floats2half2_rn(acc[t][2], acc[t][3]);
        *(__half2*)&g_h1h[(n0 + g) * 128 + c0]     = h01;
        *(__half2*)&g_h1h[(n0 + g + 8) * 128 + c0] = h23;
        float as0 = a_src1[c0], as1 = a_src1[c0 + 1];
        float ad0 = a_dst1[c0], ad1 = a_dst1[c0 + 1];
        psg  += acc[t][0] * as0 + acc[t][1] * as1;
        psg8 += acc[t][2] * as0 + acc[t][3] * as1;
        pdg  += acc[t][0] * ad0 + acc[t][1] * ad1;
        pdg8 += acc[t][2] * ad0 + acc[t][3] * ad1;
    }
    psg  += __shfl_down_sync(FULL, psg, 2, 4);  psg  += __shfl_down_sync(FULL, psg, 1, 4);
    psg8 += __shfl_down_sync(FULL, psg8, 2, 4); psg8 += __shfl_down_sync(FULL, psg8, 1, 4);
    pdg  += __shfl_down_sync(FULL, pdg, 2, 4);  pdg  += __shfl_down_sync(FULL, pdg, 1, 4);
    pdg8 += __shfl_down_sync(FULL, pdg8, 2, 4); pdg8 += __shfl_down_sync(FULL, pdg8, 1, 4);
    if (tg == 0) {
        g_als1[(n0 + g) * 4 + w]     = psg;
        g_als1[(n0 + g + 8) * 4 + w] = psg8;
        g_ald1[(n0 + g) * 4 + w]     = pdg;
        g_ald1[(n0 + g + 8) * 4 + w] = pdg8;
    }
}

// ---------------- launch 3 (PROFILED): gather1, 8 lanes/edge, HFMA2 accumulate ----------------
// warp per dst node; lane = (slot: edge j+slot, sub: 16-half col chunk).
__global__ void __launch_bounds__(256) k_edge1(const float* __restrict__ b1) {
    int tid = threadIdx.x;
    int lane = tid & 31;
    int d = (blockIdx.x << 3) + (tid >> 5);
    int slot = lane >> 3;          // 0..3
    int sub  = lane & 7;           // 0..7 -> cols [16*sub, 16*sub+16)
    int head = sub >> 1;

    float ald = g_ald1[4 * d + head];
    int beg = g_rowptr[d], end = g_rowptr[d + 1];
    const uint4* rows = (const uint4*)g_h1h;   // 16 uint4 per 128-half row

    __half2 acc[8];
#pragma unroll
    for (int q = 0; q < 8; q++) acc[q] = __float2half2_rn(0.f);
    float den = 0.f;

    for (int j = beg; j < end; j += 4) {
        int jj = j + slot;
        bool valid = jj < end;
        int s = g_csr[valid ? jj : beg];
        float l = g_als1[4 * s + head];
        uint4 r0 = rows[(s << 4) + 2 * sub];
        uint4 r1 = rows[(s << 4) + 2 * sub + 1];
        float wv = valid ? __expf(lrelu(l + ald)) : 0.f;
        den += wv;
        __half2 w2 = __float2half2_rn(wv);
        const __half2* h0 = (const __half2*)&r0;
        const __half2* h1 = (const __half2*)&r1;
#pragma unroll
        for (int q = 0; q < 4; q++) acc[q] = __hfma2(h0[q], w2, acc[q]);
#pragma unroll
        for (int q = 0; q < 4; q++) acc[4 + q] = __hfma2(h1[q], w2, acc[4 + q]);
    }

    // reduce across the 4 slots (strides 8, 16)
#pragma unroll
    for (int off = 8; off <= 16; off <<= 1) {
        den += __shfl_xor_sync(FULL, den, off);
#pragma unroll
        for (int q = 0; q < 8; q++) acc[q] = __hadd2(acc[q], h2shfl_xor(acc[q], off));
    }

    float inv = 1.f / den;
    int c0 = sub * 16;
    unsigned outw[8];
#pragma unroll
    for (int q = 0; q < 8; q++) {
        float2 f = __half22float2(acc[q]);
        float vx = eluf(f.x * inv + b1[c0 + 2 * q]);
        float vy = eluf(f.y * inv + b1[c0 + 2 * q + 1]);
        outw[q] = packh2(make_float2(vx, vy));
    }
    if (slot == 0) {
        uint4* dst = (uint4*)g_act;
        dst[(d << 4) + 2 * sub]     = make_uint4(outw[0], outw[1], outw[2], outw[3]);
        dst[(d << 4) + 2 * sub + 1] = make_uint4(outw[4], outw[5], outw[6], outw[7]);
    }
}

// ---------------- launch 4: gemm2 (lane-per-node) h2 = act @ W2 + logits2 ----------------
__global__ void __launch_bounds__(128) k_gemm2(const float* __restrict__ W2,
                                               const float* __restrict__ a2s,
                                               const float* __restrict__ a2d) {
    __shared__ unsigned int saT[64 * 129];
    __shared__ float2 sw[128 * 16];
    int tid = threadIdx.x;
    int nb = blockIdx.x * 128;

    for (int i = tid; i < 2048; i += 128) sw[i] = ((const float2*)W2)[i];
    const unsigned int* actv = (const unsigned int*)g_act;
    for (int idx = tid; idx < 128 * 64; idx += 128) {
        int node = idx >> 6, k2 = idx & 63;
        saT[k2 * 129 + node] = actv[((nb + node) << 6) + k2];
    }
    __syncthreads();

    int nloc = tid;
    int n = nb + nloc;

    unsigned long long o2[16];
#pragma unroll
    for (int i = 0; i < 16; i++) o2[i] = 0ull;

    for (int k2 = 0; k2 < 64; k2++) {
        unsigned int av = saT[k2 * 129 + nloc];
        float2 af = __half22float2(*(__half2*)&av);
        unsigned long long alo = packf2(af.x, af.x);
        unsigned long long ahi = packf2(af.y, af.y);
        const float2* w0p = &sw[(2 * k2) * 16];
#pragma unroll
        for (int cp = 0; cp < 16; cp++) {
            float2 w0 = w0p[cp];
            float2 w1 = w0p[16 + cp];
            FMA_F32X2(o2[cp], alo, packf2(w0.x, w0.y), o2[cp]);
            FMA_F32X2(o2[cp], ahi, packf2(w1.x, w1.y), o2[cp]);
        }
    }

    float ps = 0.f, pd = 0.f;
    unsigned int hp[16];
#pragma unroll
    for (int cp = 0; cp < 16; cp++) {
        float2 o = unpackf2(o2[cp]);
        hp[cp] = packh2(o);
        ps += o.x * a2s[2 * cp] + o.y * a2s[2 * cp + 1];
        pd += o.x * a2d[2 * cp] + o.y * a2d[2 * cp + 1];
    }
    uint4* h2o = (uint4*)&g_h2h[n * 32];
#pragma unroll
    for (int q = 0; q < 4; q++)
        h2o[q] = make_uint4(hp[4 * q], hp[4 * q + 1], hp[4 * q + 2], hp[4 * q + 3]);
    g_als2[n] = ps;
    g_ald2[n] = pd;
}

// ---------------- launch 5: gather2, 4 lanes/edge, HFMA2; pooled reduction ----------------
__global__ void __launch_bounds__(256) k_edge2(const float* __restrict__ b2) {
    int lane = threadIdx.x & 31;
    int d = (blockIdx.x << 3) + (threadIdx.x >> 5);
    int slot = lane >> 2;          // 0..7
    int sub  = lane & 3;           // 0..3 -> cols [8*sub, 8*sub+8)

    float ald = g_ald2[d];
    int beg = g_rowptr[d], end = g_rowptr[d + 1];
    const uint4* rows = (const uint4*)g_h2h;   // 4 uint4 per 32-half row

    __half2 acc[4];
#pragma unroll
    for (int q = 0; q < 4; q++) acc[q] = __float2half2_rn(0.f);
    float den = 0.f;

    for (int j = beg; j < end; j += 8) {
        int jj = j + slot;
        bool valid = jj < end;
        int s = g_csr[valid ? jj : beg];
        float l = g_als2[s];
        uint4 r = rows[(s << 2) + sub];
        float wv = valid ? __expf(lrelu(l + ald)) : 0.f;
        den += wv;
        __half2 w2 = __float2half2_rn(wv);
        const __half2* h = (const __half2*)&r;
#pragma unroll
        for (int q = 0; q < 4; q++) acc[q] = __hfma2(h[q], w2, acc[q]);
    }

    // reduce across the 8 slots (strides 4, 8, 16)
#pragma unroll
    for (int off = 4; off <= 16; off <<= 1) {
        den += __shfl_xor_sync(FULL, den, off);
#pragma unroll
        for (int q = 0; q < 4; q++) acc[q] = __hadd2(acc[q], h2shfl_xor(acc[q], off));
    }

    if (slot == 0) {
        float inv = 1.f / den;
        int g = d / 400;
        int c0 = sub * 8;
#pragma unroll
        for (int q = 0; q < 4; q++) {
            float2 f = __half22float2(acc[q]);
            atomicAdd(&g_pool[g * 32 + c0 + 2 * q],     eluf(f.x * inv + b2[c0 + 2 * q]));
            atomicAdd(&g_pool[g * 32 + c0 + 2 * q + 1], eluf(f.y * inv + b2[c0 + 2 * q + 1]));
        }
    }
}

// ---------------- launch 6: classifier MLP (resets g_pool) ----------------
__global__ void k_mlp(const float* __restrict__ clinical,
                      const float* __restrict__ Wc1,
                      const float* __restrict__ bc1,
                      const float* __restrict__ Wc2,
                      const float* __restrict__ bc2,
                      float* __restrict__ out) {
    int g = blockIdx.x;
    int t = threadIdx.x;
    __shared__ float sf[37];
    __shared__ float sz[16];
    if (t < 32) {
        sf[t] = g_pool[g * 32 + t] * (1.f / 400.f);
        g_pool[g * 32 + t] = 0.f;
    } else if (t < 37) {
        sf[t] = clinical[g * 5 + (t - 32)];
    }
    __syncthreads();
    if (t < 16) {
        float z = bc1[t];
#pragma unroll
        for (int i = 0; i < 37; i++) z += sf[i] * Wc1[i * 16 + t];
        sz[t] = eluf(z);
    }
    __syncthreads();
    if (t == 0) {
        float o = bc2[0];
#pragma unroll
        for (int j = 0; j < 16; j++) o += sz[j] * Wc2[j];
        out[g] = o;
    }
}

// ---------------- launch ----------------
extern "C" void kernel_launch(void* const* d_in, const int* in_sizes, int n_in,
                              void* d_out, int out_size) {
    const float* x        = (const float*)d_in[0];
    const int*   ei       = (const int*)d_in[1];
    const float* clinical = (const float*)d_in[3];
    const float* W1       = (const float*)d_in[4];
    const float* a_src1   = (const float*)d_in[5];
    const float* a_dst1   = (const float*)d_in[6];
    const float* b1       = (const float*)d_in[7];
    const float* W2       = (const float*)d_in[8];
    const float* a_src2   = (const float*)d_in[9];
    const float* a_dst2   = (const float*)d_in[10];
    const float* b2       = (const float*)d_in[11];
    const float* Wc1      = (const float*)d_in[12];
    const float* bc1      = (const float*)d_in[13];
    const float* Wc2      = (const float*)d_in[14];
    const float* bc2      = (const float*)d_in[15];
    float* out = (float*)d_out;

    k_hist<<<(EE / 4 + 255) / 256, 256>>>(ei);
    k_scan<<<1, 1024>>>(W1);
    k_scatter_gemm1<<<SCAT_BLOCKS + NN / 16, 128>>>(ei, x, a_src1, a_dst1);
    k_edge1<<<NN / 8, 256>>>(b1);                       // idx 3 -> profiled
    k_gemm2<<<NN / 128, 128>>>(W2, a_src2, a_dst2);
    k_edge2<<<NN / 8, 256>>>(b2);
    k_mlp<<<GG, 64>>>(clinical, Wc1, bc1, Wc2, bc2, out);
}

// round 11
// speedup vs baseline: 1.4891x; 1.4891x over previous
#include <cuda_runtime.h>
#include <cuda_fp16.h>

#define NN 102400
#define EE 1638400
#define ET (EE + NN)
#define GG 256
#define FULL 0xffffffffu

// ---------------- scratch (device globals; no allocation) ----------------
// Invariant: g_cnt and g_pool are ZERO at entry of every kernel_launch call.
__device__ __align__(16) __half g_h1h[NN * 128];
__device__ __align__(16) float  g_als1[NN * 4];
__device__ __align__(16) float  g_ald1[NN * 4];
__device__ __align__(16) __half g_act[NN * 128];
__device__ __align__(16) __half g_h2h[NN * 32];
__device__ __align__(16) float  g_als2[NN];
__device__ __align__(16) float  g_ald2[NN];
__device__ __align__(16) int    g_cnt[NN];
__device__ __align__(16) int    g_rowptr[NN + 4];
__device__ __align__(16) int    g_pos[NN];
__device__ __align__(16) int    g_csr[ET];
__device__ __align__(16) float  g_pool[GG * 32];
__device__ __align__(16) __half g_w1t[128 * 64];   // W1 transposed, fp16: [col][k]

__device__ __forceinline__ float eluf(float v) {
    return (v > 0.f) ? v : (__expf(v) - 1.f);
}
__device__ __forceinline__ float lrelu(float e) {
    return (e > 0.f) ? e : 0.2f * e;
}

#define FMA_F32X2(d, a, b, c) \
    asm("fma.rn.f32x2 %0, %1, %2, %3;" : "=l"(d) : "l"(a), "l"(b), "l"(c))

__device__ __forceinline__ unsigned long long packf2(float lo, float hi) {
    unsigned long long r;
    asm("mov.b64 %0, {%1, %2};" : "=l"(r) : "r"(__float_as_uint(lo)), "r"(__float_as_uint(hi)));
    return r;
}
__device__ __forceinline__ float2 unpackf2(unsigned long long v) {
    unsigned int lo, hi;
    asm("mov.b64 {%0, %1}, %2;" : "=r"(lo), "=r"(hi) : "l"(v));
    return make_float2(__uint_as_float(lo), __uint_as_float(hi));
}
__device__ __forceinline__ unsigned int packh2(float2 v) {
    __half2 h = __floats2half2_rn(v.x, v.y);
    return *(unsigned int*)&h;
}
__device__ __forceinline__ void mma16816(float* c,
                                         unsigned a0, unsigned a1, unsigned a2, unsigned a3,
                                         unsigned b0, unsigned b1) {
    asm volatile("mma.sync.aligned.m16n8k16.row.col.f32.f16.f16.f32 "
                 "{%0,%1,%2,%3}, {%4,%5,%6,%7}, {%8,%9}, {%0,%1,%2,%3};"
                 : "+f"(c[0]), "+f"(c[1]), "+f"(c[2]), "+f"(c[3])
                 : "r"(a0), "r"(a1), "r"(a2), "r"(a3), "r"(b0), "r"(b1));
}
__device__ __forceinline__ __half2 h2shfl_xor(__half2 v, int off) {
    unsigned u = __shfl_xor_sync(FULL, *(unsigned*)&v, off);
    return *(__half2*)&u;
}

// ---------------- launch 0: histogram of dst ----------------
__global__ void k_hist(const int* __restrict__ ei) {
    int t = blockIdx.x * blockDim.x + threadIdx.x;
    if (t < EE / 4) {
        int4 d4 = ((const int4*)(ei + EE))[t];
        atomicAdd(&g_cnt[d4.x], 1);
        atomicAdd(&g_cnt[d4.y], 1);
        atomicAdd(&g_cnt[d4.z], 1);
        atomicAdd(&g_cnt[d4.w], 1);
    }
}

// ---------------- launch 1: prefix scan (+self loops); resets g_cnt; builds W1T fp16 ----------------
__global__ void k_scan(const float* __restrict__ W1) {
    __shared__ int sp[1024];
    int t = threadIdx.x;
#pragma unroll
    for (int i = 0; i < 8; i++) {
        int idx = t * 8 + i;
        int n = idx >> 6, k = idx & 63;
        g_w1t[idx] = __float2half(W1[k * 128 + n]);
    }
    int4* cv = (int4*)(g_cnt + t * 100);
    int s = 0;
#pragma unroll
    for (int i = 0; i < 25; i++) {
        int4 c = cv[i];
        s += c.x + c.y + c.z + c.w + 4;
    }
    sp[t] = s;
    __syncthreads();
    for (int off = 1; off < 1024; off <<= 1) {
        int v = (t >= off) ? sp[t - off] : 0;
        __syncthreads();
        sp[t] += v;
        __syncthreads();
    }
    int run = t ? sp[t - 1] : 0;
    int4* rp = (int4*)(g_rowptr + t * 100);
    int4* pp = (int4*)(g_pos + t * 100);
    int4 zero = make_int4(0, 0, 0, 0);
#pragma unroll
    for (int i = 0; i < 25; i++) {
        int4 c = cv[i];
        int4 r;
        r.x = run; run += c.x + 1;
        r.y = run; run += c.y + 1;
        r.z = run; run += c.z + 1;
        r.w = run; run += c.w + 1;
        rp[i] = r;
        pp[i] = r;
        cv[i] = zero;
    }
    if (t == 1023) g_rowptr[NN] = ET;
}

// ---------------- launch 2: scatter CSR + tensor-core gemm1 ----------------
#define SCAT_BLOCKS 4000
__global__ void __launch_bounds__(128) k_scatter_gemm1(
        const int* __restrict__ ei,
        const float* __restrict__ x,
        const float* __restrict__ a_src1,
        const float* __restrict__ a_dst1) {
    if (blockIdx.x < SCAT_BLOCKS) {
        int t = blockIdx.x * 128 + threadIdx.x;
        const int Q = EE / 4;
        if (t < Q) {
            int4 s4 = ((const int4*)ei)[t];
            int4 d4 = ((const int4*)(ei + EE))[t];
            int p;
            p = atomicAdd(&g_pos[d4.x], 1); g_csr[p] = s4.x;
            p = atomicAdd(&g_pos[d4.y], 1); g_csr[p] = s4.y;
            p = atomicAdd(&g_pos[d4.z], 1); g_csr[p] = s4.z;
            p = atomicAdd(&g_pos[d4.w], 1); g_csr[p] = s4.w;
        } else {
            int n = t - Q;
            int p = atomicAdd(&g_pos[n], 1);
            g_csr[p] = n;
        }
        return;
    }
    int bid = blockIdx.x - SCAT_BLOCKS;
    int n0 = bid * 16;
    int w = threadIdx.x >> 5;
    int l = threadIdx.x & 31;
    int g = l >> 2, tg = l & 3;

    const float2* xg  = (const float2*)(x + (n0 + g) * 64);
    const float2* xg8 = (const float2*)(x + (n0 + g + 8) * 64);

    float acc[4][4];
#pragma unroll
    for (int t = 0; t < 4; t++)
#pragma unroll
        for (int i = 0; i < 4; i++) acc[t][i] = 0.f;

#pragma unroll
    for (int ks = 0; ks < 4; ks++) {
        unsigned a0 = packh2(xg [8 * ks + tg]);
        unsigned a1 = packh2(xg8[8 * ks + tg]);
        unsigned a2 = packh2(xg [8 * ks + tg + 4]);
        unsigned a3 = packh2(xg8[8 * ks + tg + 4]);
#pragma unroll
        for (int t = 0; t < 4; t++) {
            int col = 32 * w + 8 * t + g;
            unsigned b0 = *(const unsigned*)&g_w1t[col * 64 + 16 * ks + 2 * tg];
            unsigned b1 = *(const unsigned*)&g_w1t[col * 64 + 16 * ks + 2 * tg + 8];
            mma16816(acc[t], a0, a1, a2, a3, b0, b1);
        }
    }

    float psg = 0.f, psg8 = 0.f, pdg = 0.f, pdg8 = 0.f;
#pragma unroll
    for (int t = 0; t < 4; t++) {
        int c0 = 32 * w + 8 * t + 2 * tg;
        __half2 h01 = __floats2half2_rn(acc[t][0], acc[t][1]);
        __half2 h23 = __floats2half2_rn(acc[t][2], acc[t][3]);
        *(__half2*)&g_h1h[(n0 + g) * 128 + c0]     = h01;
        *(__half2*)&g_h1h[(n0 + g + 8) * 128 + c0] = h23;
        float as0 = a_src1[c0], as1 = a_src1[c0 + 1];
        float ad0 = a_dst1[c0], ad1 = a_dst1[c0 + 1];
        psg  += acc[t][0] * as0 + acc[t][1] * as1;
        psg8 += acc[t][2] * as0 + acc[t][3] * as1;
        pdg  += acc[t][0] * ad0 + acc[t][1] * ad1;
        pdg8 += acc[t][2] * ad0 + acc[t][3] * ad1;
    }
    psg  += __shfl_down_sync(FULL, psg, 2, 4);  psg  += __shfl_down_sync(FULL, psg, 1, 4);
    psg8 += __shfl_down_sync(FULL, psg8, 2, 4); psg8 += __shfl_down_sync(FULL, psg8, 1, 4);
    pdg  += __shfl_down_sync(FULL, pdg, 2, 4);  pdg  += __shfl_down_sync(FULL, pdg, 1, 4);
    pdg8 += __shfl_down_sync(FULL, pdg8, 2, 4); pdg8 += __shfl_down_sync(FULL, pdg8, 1, 4);
    if (tg == 0) {
        g_als1[(n0 + g) * 4 + w]     = psg;
        g_als1[(n0 + g + 8) * 4 + w] = psg8;
        g_ald1[(n0 + g) * 4 + w]     = pdg;
        g_ald1[(n0 + g + 8) * 4 + w] = pdg8;
    }
}

// ---------------- launch 3 (PROFILED): gather1 (R9 structure, HFMA2 accumulate) ----------------
// warp per dst node, batch-4 edges, lane covers 4 halves via float2 load.
__global__ void __launch_bounds__(256) k_edge1(const float* __restrict__ b1) {
    int tid = threadIdx.x;
    int lane = tid & 31;
    int d = (blockIdx.x << 3) + (tid >> 5);
    int head = lane >> 3;

    const float2* h1v = (const float2*)g_h1h;

    float ald = g_ald1[4 * d + head];
    int beg = g_rowptr[d], end = g_rowptr[d + 1];
    int pad = g_csr[beg];
    __half2 a01 = __float2half2_rn(0.f);
    __half2 a23 = __float2half2_rn(0.f);
    float den = 0.f;

    for (int j = beg; j < end; j += 4) {
        int s0 = (j     < end) ? g_csr[j]     : pad;
        int s1 = (j + 1 < end) ? g_csr[j + 1] : pad;
        int s2 = (j + 2 < end) ? g_csr[j + 2] : pad;
        int s3 = (j + 3 < end) ? g_csr[j + 3] : pad;
        float l0 = g_als1[4 * s0 + head];
        float l1 = g_als1[4 * s1 + head];
        float l2 = g_als1[4 * s2 + head];
        float l3 = g_als1[4 * s3 + head];
        float2 r0 = h1v[(s0 << 5) + lane];
        float2 r1 = h1v[(s1 << 5) + lane];
        float2 r2 = h1v[(s2 << 5) + lane];
        float2 r3 = h1v[(s3 << 5) + lane];
        float w0 = (j     < end) ? __expf(lrelu(l0 + ald)) : 0.f;
        float w1 = (j + 1 < end) ? __expf(lrelu(l1 + ald)) : 0.f;
        float w2 = (j + 2 < end) ? __expf(lrelu(l2 + ald)) : 0.f;
        float w3 = (j + 3 < end) ? __expf(lrelu(l3 + ald)) : 0.f;
        den += (w0 + w1) + (w2 + w3);
        __half2 h0 = __float2half2_rn(w0);
        __half2 h1w = __float2half2_rn(w1);
        __half2 h2w = __float2half2_rn(w2);
        __half2 h3w = __float2half2_rn(w3);
        a01 = __hfma2(*(__half2*)&r0.x, h0, a01);
        a23 = __hfma2(*(__half2*)&r0.y, h0, a23);
        a01 = __hfma2(*(__half2*)&r1.x, h1w, a01);
        a23 = __hfma2(*(__half2*)&r1.y, h1w, a23);
        a01 = __hfma2(*(__half2*)&r2.x, h2w, a01);
        a23 = __hfma2(*(__half2*)&r2.y, h2w, a23);
        a01 = __hfma2(*(__half2*)&r3.x, h3w, a01);
        a23 = __hfma2(*(__half2*)&r3.y, h3w, a23);
    }

    float inv = 1.f / den;
    float4 bb = *(const float4*)&b1[lane * 4];
    float2 f01 = __half22float2(a01);
    float2 f23 = __half22float2(a23);
    __half2 p0 = __floats2half2_rn(eluf(f01.x * inv + bb.x), eluf(f01.y * inv + bb.y));
    __half2 p1 = __floats2half2_rn(eluf(f23.x * inv + bb.z), eluf(f23.y * inv + bb.w));
    uint2 st;
    st.x = *(unsigned int*)&p0;
    st.y = *(unsigned int*)&p1;
    ((uint2*)g_act)[(d << 5) + lane] = st;
}

// ---------------- launch 4: gemm2 (lane-per-node) h2 = act @ W2 + logits2 ----------------
__global__ void __launch_bounds__(128) k_gemm2(const float* __restrict__ W2,
                                               const float* __restrict__ a2s,
                                               const float* __restrict__ a2d) {
    __shared__ unsigned int saT[64 * 129];
    __shared__ float2 sw[128 * 16];
    int tid = threadIdx.x;
    int nb = blockIdx.x * 128;

    for (int i = tid; i < 2048; i += 128) sw[i] = ((const float2*)W2)[i];
    const unsigned int* actv = (const unsigned int*)g_act;
    for (int idx = tid; idx < 128 * 64; idx += 128) {
        int node = idx >> 6, k2 = idx & 63;
        saT[k2 * 129 + node] = actv[((nb + node) << 6) + k2];
    }
    __syncthreads();

    int nloc = tid;
    int n = nb + nloc;

    unsigned long long o2[16];
#pragma unroll
    for (int i = 0; i < 16; i++) o2[i] = 0ull;

    for (int k2 = 0; k2 < 64; k2++) {
        unsigned int av = saT[k2 * 129 + nloc];
        float2 af = __half22float2(*(__half2*)&av);
        unsigned long long alo = packf2(af.x, af.x);
        unsigned long long ahi = packf2(af.y, af.y);
        const float2* w0p = &sw[(2 * k2) * 16];
#pragma unroll
        for (int cp = 0; cp < 16; cp++) {
            float2 w0 = w0p[cp];
            float2 w1 = w0p[16 + cp];
            FMA_F32X2(o2[cp], alo, packf2(w0.x, w0.y), o2[cp]);
            FMA_F32X2(o2[cp], ahi, packf2(w1.x, w1.y), o2[cp]);
        }
    }

    float ps = 0.f, pd = 0.f;
    unsigned int hp[16];
#pragma unroll
    for (int cp = 0; cp < 16; cp++) {
        float2 o = unpackf2(o2[cp]);
        hp[cp] = packh2(o);
        ps += o.x * a2s[2 * cp] + o.y * a2s[2 * cp + 1];
        pd += o.x * a2d[2 * cp] + o.y * a2d[2 * cp + 1];
    }
    uint4* h2o = (uint4*)&g_h2h[n * 32];
#pragma unroll
    for (int q = 0; q < 4; q++)
        h2o[q] = make_uint4(hp[4 * q], hp[4 * q + 1], hp[4 * q + 2], hp[4 * q + 3]);
    g_als2[n] = ps;
    g_ald2[n] = pd;
}

// ---------------- launch 5: gather2 (R9 structure, HFMA2 accumulate) ----------------
// warp per dst node, half-warp per edge, unrolled x2 (4 edges in flight).
__global__ void __launch_bounds__(256) k_edge2(const float* __restrict__ b2) {
    int lane = threadIdx.x & 31;
    int d = (blockIdx.x << 3) + (threadIdx.x >> 5);
    int hw = lane >> 4;
    int c2 = (lane & 15) << 1;
    float ald = g_ald2[d];
    int beg = g_rowptr[d], end = g_rowptr[d + 1];
    __half2 acc = __float2half2_rn(0.f);
    float den = 0.f;
    int j = beg;
    for (; j + 4 <= end; j += 4) {
        int s0 = g_csr[j + hw];
        int s1 = g_csr[j + 2 + hw];
        float l0 = g_als2[s0];
        float l1 = g_als2[s1];
        __half2 v0 = *(const __half2*)(g_h2h + s0 * 32 + c2);
        __half2 v1 = *(const __half2*)(g_h2h + s1 * 32 + c2);
        float w0 = __expf(lrelu(l0 + ald));
        float w1 = __expf(lrelu(l1 + ald));
        den += w0 + w1;
        acc = __hfma2(v0, __float2half2_rn(w0), acc);
        acc = __hfma2(v1, __float2half2_rn(w1), acc);
    }
    for (; j < end; j += 2) {
        int jj = j + hw;
        bool valid = jj < end;
        int s = g_csr[valid ? jj : beg];
        float e = lrelu(g_als2[s] + ald);
        float wv = valid ? __expf(e) : 0.f;
        den += wv;
        __half2 hv = *(const __half2*)(g_h2h + s * 32 + c2);
        acc = __hfma2(hv, __float2half2_rn(wv), acc);
    }
    den += __shfl_xor_sync(FULL, den, 16);
    acc = __hadd2(acc, h2shfl_xor(acc, 16));
    if (hw == 0) {
        float inv = 1.f / den;
        float2 f = __half22float2(acc);
        float vx = eluf(f.x * inv + b2[c2]);
        float vy = eluf(f.y * inv + b2[c2 + 1]);
        int g = d / 400;
        atomicAdd(&g_pool[g * 32 + c2], vx);
        atomicAdd(&g_pool[g * 32 + c2 + 1], vy);
    }
}

// ---------------- launch 6: classifier MLP (resets g_pool) ----------------
__global__ void k_mlp(const float* __restrict__ clinical,
                      const float* __restrict__ Wc1,
                      const float* __restrict__ bc1,
                      const float* __restrict__ Wc2,
                      const float* __restrict__ bc2,
                      float* __restrict__ out) {
    int g = blockIdx.x;
    int t = threadIdx.x;
    __shared__ float sf[37];
    __shared__ float sz[16];
    if (t < 32) {
        sf[t] = g_pool[g * 32 + t] * (1.f / 400.f);
        g_pool[g * 32 + t] = 0.f;
    } else if (t < 37) {
        sf[t] = clinical[g * 5 + (t - 32)];
    }
    __syncthreads();
    if (t < 16) {
        float z = bc1[t];
#pragma unroll
        for (int i = 0; i < 37; i++) z += sf[i] * Wc1[i * 16 + t];
        sz[t] = eluf(z);
    }
    __syncthreads();
    if (t == 0) {
        float o = bc2[0];
#pragma unroll
        for (int j = 0; j < 16; j++) o += sz[j] * Wc2[j];
        out[g] = o;
    }
}

// ---------------- launch ----------------
extern "C" void kernel_launch(void* const* d_in, const int* in_sizes, int n_in,
                              void* d_out, int out_size) {
    const float* x        = (const float*)d_in[0];
    const int*   ei       = (const int*)d_in[1];
    const float* clinical = (const float*)d_in[3];
    const float* W1       = (const float*)d_in[4];
    const float* a_src1   = (const float*)d_in[5];
    const float* a_dst1   = (const float*)d_in[6];
    const float* b1       = (const float*)d_in[7];
    const float* W2       = (const float*)d_in[8];
    const float* a_src2   = (const float*)d_in[9];
    const float* a_dst2   = (const float*)d_in[10];
    const float* b2       = (const float*)d_in[11];
    const float* Wc1      = (const float*)d_in[12];
    const float* bc1      = (const float*)d_in[13];
    const float* Wc2      = (const float*)d_in[14];
    const float* bc2      = (const float*)d_in[15];
    float* out = (float*)d_out;

    k_hist<<<(EE / 4 + 255) / 256, 256>>>(ei);
    k_scan<<<1, 1024>>>(W1);
    k_scatter_gemm1<<<SCAT_BLOCKS + NN / 16, 128>>>(ei, x, a_src1, a_dst1);
    k_edge1<<<NN / 8, 256>>>(b1);                       // idx 3 -> profiled
    k_gemm2<<<NN / 128, 128>>>(W2, a_src2, a_dst2);
    k_edge2<<<NN / 8, 256>>>(b2);
    k_mlp<<<GG, 64>>>(clinical, Wc1, bc1, Wc2, bc2, out);
}

// round 12
// speedup vs baseline: 1.5291x; 1.0268x over previous
#include <cuda_runtime.h>
#include <cuda_fp16.h>

#define NN 102400
#define EE 1638400
#define ET (EE + NN)
#define ET_PAD (ET + 3 * NN)      // 2,048,000: worst-case padded CSR
#define GG 256
#define FULL 0xffffffffu
#define NEG_INF __int_as_float(0xff800000)

// ---------------- scratch (device globals; no allocation) ----------------
// Invariant: g_cnt and g_pool are ZERO at entry of every kernel_launch call.
// Rows NN of g_h1h / g_h2h are NEVER written -> remain zero (dummy pad node).
__device__ __align__(16) __half g_h1h[(NN + 1) * 128];
__device__ __align__(16) float  g_als1[(NN + 1) * 4];
__device__ __align__(16) float  g_ald1[NN * 4];
__device__ __align__(16) __half g_act[NN * 128];
__device__ __align__(16) __half g_h2h[(NN + 1) * 32];
__device__ __align__(16) float  g_als2[NN + 1];
__device__ __align__(16) float  g_ald2[NN];
__device__ __align__(16) int    g_cnt[NN];
__device__ __align__(16) int    g_rowptr[NN + 4];
__device__ __align__(16) int    g_pos[NN];
__device__ __align__(16) int    g_csr[ET_PAD];
__device__ __align__(16) float  g_pool[GG * 32];
__device__ __align__(16) __half g_w1t[128 * 64];

__device__ __forceinline__ float eluf(float v) {
    return (v > 0.f) ? v : (__expf(v) - 1.f);
}

#define FMA_F32X2(d, a, b, c) \
    asm("fma.rn.f32x2 %0, %1, %2, %3;" : "=l"(d) : "l"(a), "l"(b), "l"(c))

__device__ __forceinline__ unsigned long long packf2(float lo, float hi) {
    unsigned long long r;
    asm("mov.b64 %0, {%1, %2};" : "=l"(r) : "r"(__float_as_uint(lo)), "r"(__float_as_uint(hi)));
    return r;
}
__device__ __forceinline__ float2 unpackf2(unsigned long long v) {
    unsigned int lo, hi;
    asm("mov.b64 {%0, %1}, %2;" : "=r"(lo), "=r"(hi) : "l"(v));
    return make_float2(__uint_as_float(lo), __uint_as_float(hi));
}
__device__ __forceinline__ unsigned int packh2(float2 v) {
    __half2 h = __floats2half2_rn(v.x, v.y);
    return *(unsigned int*)&h;
}
__device__ __forceinline__ void mma16816(float* c,
                                         unsigned a0, unsigned a1, unsigned a2, unsigned a3,
                                         unsigned b0, unsigned b1) {
    asm volatile("mma.sync.aligned.m16n8k16.row.col.f32.f16.f16.f32 "
                 "{%0,%1,%2,%3}, {%4,%5,%6,%7}, {%8,%9}, {%0,%1,%2,%3};"
                 : "+f"(c[0]), "+f"(c[1]), "+f"(c[2]), "+f"(c[3])
                 : "r"(a0), "r"(a1), "r"(a2), "r"(a3), "r"(b0), "r"(b1));
}
__device__ __forceinline__ __half2 h2shfl_xor(__half2 v, int off) {
    unsigned u = __shfl_xor_sync(FULL, *(unsigned*)&v, off);
    return *(__half2*)&u;
}
// exp(lrelu(e)); returns 0 for e = -inf (pad edges)
__device__ __forceinline__ float wexp(float e) {
    return __expf(fmaxf(e, 0.2f * e));
}

// ---------------- launch 0: histogram of dst + prefill padded CSR with dummy NN ----------------
__global__ void k_hist(const int* __restrict__ ei) {
    int t = blockIdx.x * blockDim.x + threadIdx.x;   // grid covers ET_PAD/4 = 512000
    ((int4*)g_csr)[t] = make_int4(NN, NN, NN, NN);
    if (t < EE / 4) {
        int4 d4 = ((const int4*)(ei + EE))[t];
        atomicAdd(&g_cnt[d4.x], 1);
        atomicAdd(&g_cnt[d4.y], 1);
        atomicAdd(&g_cnt[d4.z], 1);
        atomicAdd(&g_cnt[d4.w], 1);
    }
}

// ---------------- launch 1: padded prefix scan; resets g_cnt; W1T fp16; -inf pad logits ----------------
__global__ void k_scan(const float* __restrict__ W1) {
    __shared__ int sp[1024];
    int t = threadIdx.x;
#pragma unroll
    for (int i = 0; i < 8; i++) {
        int idx = t * 8 + i;
        int n = idx >> 6, k = idx & 63;
        g_w1t[idx] = __float2half(W1[k * 128 + n]);
    }
    if (t == 0) {
        g_als1[4 * NN]     = NEG_INF;
        g_als1[4 * NN + 1] = NEG_INF;
        g_als1[4 * NN + 2] = NEG_INF;
        g_als1[4 * NN + 3] = NEG_INF;
        g_als2[NN] = NEG_INF;
    }
    int4* cv = (int4*)(g_cnt + t * 100);
    int s = 0;
#pragma unroll
    for (int i = 0; i < 25; i++) {
        int4 c = cv[i];
        s += ((c.x + 4) & ~3) + ((c.y + 4) & ~3) + ((c.z + 4) & ~3) + ((c.w + 4) & ~3);
    }
    sp[t] = s;
    __syncthreads();
    for (int off = 1; off < 1024; off <<= 1) {
        int v = (t >= off) ? sp[t - off] : 0;
        __syncthreads();
        sp[t] += v;
        __syncthreads();
    }
    int run = t ? sp[t - 1] : 0;
    int4* rp = (int4*)(g_rowptr + t * 100);
    int4* pp = (int4*)(g_pos + t * 100);
    int4 zero = make_int4(0, 0, 0, 0);
#pragma unroll
    for (int i = 0; i < 25; i++) {
        int4 c = cv[i];
        int4 r;
        r.x = run; run += (c.x + 4) & ~3;
        r.y = run; run += (c.y + 4) & ~3;
        r.z = run; run += (c.z + 4) & ~3;
        r.w = run; run += (c.w + 4) & ~3;
        rp[i] = r;
        pp[i] = r;
        cv[i] = zero;
    }
    if (t == 1023) g_rowptr[NN] = run;
}

// ---------------- launch 2: scatter CSR + tensor-core gemm1 ----------------
#define SCAT_BLOCKS 4000
__global__ void __launch_bounds__(128) k_scatter_gemm1(
        const int* __restrict__ ei,
        const float* __restrict__ x,
        const float* __restrict__ a_src1,
        const float* __restrict__ a_dst1) {
    if (blockIdx.x < SCAT_BLOCKS) {
        int t = blockIdx.x * 128 + threadIdx.x;
        const int Q = EE / 4;
        if (t < Q) {
            int4 s4 = ((const int4*)ei)[t];
            int4 d4 = ((const int4*)(ei + EE))[t];
            int p;
            p = atomicAdd(&g_pos[d4.x], 1); g_csr[p] = s4.x;
            p = atomicAdd(&g_pos[d4.y], 1); g_csr[p] = s4.y;
            p = atomicAdd(&g_pos[d4.z], 1); g_csr[p] = s4.z;
            p = atomicAdd(&g_pos[d4.w], 1); g_csr[p] = s4.w;
        } else {
            int n = t - Q;
            int p = atomicAdd(&g_pos[n], 1);
            g_csr[p] = n;
        }
        return;
    }
    int bid = blockIdx.x - SCAT_BLOCKS;
    int n0 = bid * 16;
    int w = threadIdx.x >> 5;
    int l = threadIdx.x & 31;
    int g = l >> 2, tg = l & 3;

    const float2* xg  = (const float2*)(x + (n0 + g) * 64);
    const float2* xg8 = (const float2*)(x + (n0 + g + 8) * 64);

    float acc[4][4];
#pragma unroll
    for (int t = 0; t < 4; t++)
#pragma unroll
        for (int i = 0; i < 4; i++) acc[t][i] = 0.f;

#pragma unroll
    for (int ks = 0; ks < 4; ks++) {
        unsigned a0 = packh2(xg [8 * ks + tg]);
        unsigned a1 = packh2(xg8[8 * ks + tg]);
        unsigned a2 = packh2(xg [8 * ks + tg + 4]);
        unsigned a3 = packh2(xg8[8 * ks + tg + 4]);
#pragma unroll
        for (int t = 0; t < 4; t++) {
            int col = 32 * w + 8 * t + g;
            unsigned b0 = *(const unsigned*)&g_w1t[col * 64 + 16 * ks + 2 * tg];
            unsigned b1 = *(const unsigned*)&g_w1t[col * 64 + 16 * ks + 2 * tg + 8];
            mma16816(acc[t], a0, a1, a2, a3, b0, b1);
        }
    }

    float psg = 0.f, psg8 = 0.f, pdg = 0.f, pdg8 = 0.f;
#pragma unroll
    for (int t = 0; t < 4; t++) {
        int c0 = 32 * w + 8 * t + 2 * tg;
        __half2 h01 = __floats2half2_rn(acc[t][0], acc[t][1]);
        __half2 h23 = __floats2half2_rn(acc[t][2], acc[t][3]);
        *(__half2*)&g_h1h[(n0 + g) * 128 + c0]     = h01;
        *(__half2*)&g_h1h[(n0 + g + 8) * 128 + c0] = h23;
        float as0 = a_src1[c0], as1 = a_src1[c0 + 1];
        float ad0 = a_dst1[c0], ad1 = a_dst1[c0 + 1];
        psg  += acc[t][0] * as0 + acc[t][1] * as1;
        psg8 += acc[t][2] * as0 + acc[t][3] * as1;
        pdg  += acc[t][0] * ad0 + acc[t][1] * ad1;
        pdg8 += acc[t][2] * ad0 + acc[t][3] * ad1;
    }
    psg  += __shfl_down_sync(FULL, psg, 2, 4);  psg  += __shfl_down_sync(FULL, psg, 1, 4);
    psg8 += __shfl_down_sync(FULL, psg8, 2, 4); psg8 += __shfl_down_sync(FULL, psg8, 1, 4);
    pdg  += __shfl_down_sync(FULL, pdg, 2, 4);  pdg  += __shfl_down_sync(FULL, pdg, 1, 4);
    pdg8 += __shfl_down_sync(FULL, pdg8, 2, 4); pdg8 += __shfl_down_sync(FULL, pdg8, 1, 4);
    if (tg == 0) {
        g_als1[(n0 + g) * 4 + w]     = psg;
        g_als1[(n0 + g + 8) * 4 + w] = psg8;
        g_ald1[(n0 + g) * 4 + w]     = pdg;
        g_ald1[(n0 + g + 8) * 4 + w] = pdg8;
    }
}

// ---------------- launch 3 (PROFILED): gather1, branchless padded batches of 4 ----------------
__global__ void __launch_bounds__(256) k_edge1(const float* __restrict__ b1) {
    int tid = threadIdx.x;
    int lane = tid & 31;
    int d = (blockIdx.x << 3) + (tid >> 5);
    int head = lane >> 3;

    const float2* h1v = (const float2*)g_h1h;

    float ald = g_ald1[4 * d + head];
    int beg = g_rowptr[d], end = g_rowptr[d + 1];
    __half2 a01 = __float2half2_rn(0.f);
    __half2 a23 = __float2half2_rn(0.f);
    float den = 0.f;

    for (int j = beg; j < end; j += 4) {
        int4 s4 = *(const int4*)&g_csr[j];
        float l0 = g_als1[4 * s4.x + head];
        float l1 = g_als1[4 * s4.y + head];
        float l2 = g_als1[4 * s4.z + head];
        float l3 = g_als1[4 * s4.w + head];
        float2 r0 = h1v[(s4.x << 5) + lane];
        float2 r1 = h1v[(s4.y << 5) + lane];
        float2 r2 = h1v[(s4.z << 5) + lane];
        float2 r3 = h1v[(s4.w << 5) + lane];
        float w0 = wexp(l0 + ald);
        float w1 = wexp(l1 + ald);
        float w2 = wexp(l2 + ald);
        float w3 = wexp(l3 + ald);
        den += (w0 + w1) + (w2 + w3);
        __half2 h0 = __float2half2_rn(w0);
        __half2 h1w = __float2half2_rn(w1);
        __half2 h2w = __float2half2_rn(w2);
        __half2 h3w = __float2half2_rn(w3);
        a01 = __hfma2(*(__half2*)&r0.x, h0, a01);
        a23 = __hfma2(*(__half2*)&r0.y, h0, a23);
        a01 = __hfma2(*(__half2*)&r1.x, h1w, a01);
        a23 = __hfma2(*(__half2*)&r1.y, h1w, a23);
        a01 = __hfma2(*(__half2*)&r2.x, h2w, a01);
        a23 = __hfma2(*(__half2*)&r2.y, h2w, a23);
        a01 = __hfma2(*(__half2*)&r3.x, h3w, a01);
        a23 = __hfma2(*(__half2*)&r3.y, h3w, a23);
    }

    float inv = 1.f / den;
    float4 bb = *(const float4*)&b1[lane * 4];
    float2 f01 = __half22float2(a01);
    float2 f23 = __half22float2(a23);
    __half2 p0 = __floats2half2_rn(eluf(f01.x * inv + bb.x), eluf(f01.y * inv + bb.y));
    __half2 p1 = __floats2half2_rn(eluf(f23.x * inv + bb.z), eluf(f23.y * inv + bb.w));
    uint2 st;
    st.x = *(unsigned int*)&p0;
    st.y = *(unsigned int*)&p1;
    ((uint2*)g_act)[(d << 5) + lane] = st;
}

// ---------------- launch 4: gemm2 (lane-per-node) h2 = act @ W2 + logits2 ----------------
__global__ void __launch_bounds__(128) k_gemm2(const float* __restrict__ W2,
                                               const float* __restrict__ a2s,
                                               const float* __restrict__ a2d) {
    __shared__ unsigned int saT[64 * 129];
    __shared__ float2 sw[128 * 16];
    int tid = threadIdx.x;
    int nb = blockIdx.x * 128;

    for (int i = tid; i < 2048; i += 128) sw[i] = ((const float2*)W2)[i];
    const unsigned int* actv = (const unsigned int*)g_act;
    for (int idx = tid; idx < 128 * 64; idx += 128) {
        int node = idx >> 6, k2 = idx & 63;
        saT[k2 * 129 + node] = actv[((nb + node) << 6) + k2];
    }
    __syncthreads();

    int nloc = tid;
    int n = nb + nloc;

    unsigned long long o2[16];
#pragma unroll
    for (int i = 0; i < 16; i++) o2[i] = 0ull;

    for (int k2 = 0; k2 < 64; k2++) {
        unsigned int av = saT[k2 * 129 + nloc];
        float2 af = __half22float2(*(__half2*)&av);
        unsigned long long alo = packf2(af.x, af.x);
        unsigned long long ahi = packf2(af.y, af.y);
        const float2* w0p = &sw[(2 * k2) * 16];
#pragma unroll
        for (int cp = 0; cp < 16; cp++) {
            float2 w0 = w0p[cp];
            float2 w1 = w0p[16 + cp];
            FMA_F32X2(o2[cp], alo, packf2(w0.x, w0.y), o2[cp]);
            FMA_F32X2(o2[cp], ahi, packf2(w1.x, w1.y), o2[cp]);
        }
    }

    float ps = 0.f, pd = 0.f;
    unsigned int hp[16];
#pragma unroll
    for (int cp = 0; cp < 16; cp++) {
        float2 o = unpackf2(o2[cp]);
        hp[cp] = packh2(o);
        ps += o.x * a2s[2 * cp] + o.y * a2s[2 * cp + 1];
        pd += o.x * a2d[2 * cp] + o.y * a2d[2 * cp + 1];
    }
    uint4* h2o = (uint4*)&g_h2h[n * 32];
#pragma unroll
    for (int q = 0; q < 4; q++)
        h2o[q] = make_uint4(hp[4 * q], hp[4 * q + 1], hp[4 * q + 2], hp[4 * q + 3]);
    g_als2[n] = ps;
    g_ald2[n] = pd;
}

// ---------------- launch 5: gather2, branchless padded; pooled reduction ----------------
__global__ void __launch_bounds__(256) k_edge2(const float* __restrict__ b2) {
    int lane = threadIdx.x & 31;
    int d = (blockIdx.x << 3) + (threadIdx.x >> 5);
    int hw = lane >> 4;
    int c2 = (lane & 15) << 1;
    float ald = g_ald2[d];
    int beg = g_rowptr[d], end = g_rowptr[d + 1];
    __half2 acc = __float2half2_rn(0.f);
    float den = 0.f;
    for (int j = beg; j < end; j += 4) {
        int s0 = g_csr[j + hw];
        int s1 = g_csr[j + 2 + hw];
        float l0 = g_als2[s0];
        float l1 = g_als2[s1];
        __half2 v0 = *(const __half2*)(g_h2h + s0 * 32 + c2);
        __half2 v1 = *(const __half2*)(g_h2h + s1 * 32 + c2);
        float w0 = wexp(l0 + ald);
        float w1 = wexp(l1 + ald);
        den += w0 + w1;
        acc = __hfma2(v0, __float2half2_rn(w0), acc);
        acc = __hfma2(v1, __float2half2_rn(w1), acc);
    }
    den += __shfl_xor_sync(FULL, den, 16);
    acc = __hadd2(acc, h2shfl_xor(acc, 16));
    if (hw == 0) {
        float inv = 1.f / den;
        float2 f = __half22float2(acc);
        float vx = eluf(f.x * inv + b2[c2]);
        float vy = eluf(f.y * inv + b2[c2 + 1]);
        int g = d / 400;
        atomicAdd(&g_pool[g * 32 + c2], vx);
        atomicAdd(&g_pool[g * 32 + c2 + 1], vy);
    }
}

// ---------------- launch 6: classifier MLP (resets g_pool) ----------------
__global__ void k_mlp(const float* __restrict__ clinical,
                      const float* __restrict__ Wc1,
                      const float* __restrict__ bc1,
                      const float* __restrict__ Wc2,
                      const float* __restrict__ bc2,
                      float* __restrict__ out) {
    int g = blockIdx.x;
    int t = threadIdx.x;
    __shared__ float sf[37];
    __shared__ float sz[16];
    if (t < 32) {
        sf[t] = g_pool[g * 32 + t] * (1.f / 400.f);
        g_pool[g * 32 + t] = 0.f;
    } else if (t < 37) {
        sf[t] = clinical[g * 5 + (t - 32)];
    }
    __syncthreads();
    if (t < 16) {
        float z = bc1[t];
#pragma unroll
        for (int i = 0; i < 37; i++) z += sf[i] * Wc1[i * 16 + t];
        sz[t] = eluf(z);
    }
    __syncthreads();
    if (t == 0) {
        float o = bc2[0];
#pragma unroll
        for (int j = 0; j < 16; j++) o += sz[j] * Wc2[j];
        out[g] = o;
    }
}

// ---------------- launch ----------------
extern "C" void kernel_launch(void* const* d_in, const int* in_sizes, int n_in,
                              void* d_out, int out_size) {
    const float* x        = (const float*)d_in[0];
    const int*   ei       = (const int*)d_in[1];
    const float* clinical = (const float*)d_in[3];
    const float* W1       = (const float*)d_in[4];
    const float* a_src1   = (const float*)d_in[5];
    const float* a_dst1   = (const float*)d_in[6];
    const float* b1       = (const float*)d_in[7];
    const float* W2       = (const float*)d_in[8];
    const float* a_src2   = (const float*)d_in[9];
    const float* a_dst2   = (const float*)d_in[10];
    const float* b2       = (const float*)d_in[11];
    const float* Wc1      = (const float*)d_in[12];
    const float* bc1      = (const float*)d_in[13];
    const float* Wc2      = (const float*)d_in[14];
    const float* bc2      = (const float*)d_in[15];
    float* out = (float*)d_out;

    k_hist<<<ET_PAD / 4 / 256, 256>>>(ei);              // 2000 blocks: fill + hist
    k_scan<<<1, 1024>>>(W1);
    k_scatter_gemm1<<<SCAT_BLOCKS + NN / 16, 128>>>(ei, x, a_src1, a_dst1);
    k_edge1<<<NN / 8, 256>>>(b1);                       // idx 3 -> profiled
    k_gemm2<<<NN / 128, 128>>>(W2, a_src2, a_dst2);
    k_edge2<<<NN / 8, 256>>>(b2);
    k_mlp<<<GG, 64>>>(clinical, Wc1, bc1, Wc2, bc2, out);
}

// round 13
// speedup vs baseline: 1.6124x; 1.0545x over previous
#include <cuda_runtime.h>
#include <cuda_fp16.h>

#define NN 102400
#define EE 1638400
#define ET (EE + NN)
#define ET_PAD (ET + 3 * NN)      // 2,048,000: worst-case padded CSR
#define GG 256
#define FULL 0xffffffffu
#define NEG_INF __int_as_float(0xff800000)
#define LOG2E 1.4426950408889634f

// ---------------- scratch (device globals; no allocation) ----------------
// Invariant: g_cnt and g_pool are ZERO at entry of every kernel_launch call.
// Rows NN of g_h1h / g_h2h are NEVER written -> remain zero (dummy pad node).
// NOTE: all logits (g_als1/g_ald1/g_als2/g_ald2) are stored PRE-SCALED by log2(e).
__device__ __align__(16) __half g_h1h[(NN + 1) * 128];
__device__ __align__(16) float  g_als1[(NN + 1) * 4];
__device__ __align__(16) float  g_ald1[NN * 4];
__device__ __align__(16) __half g_act[NN * 128];
__device__ __align__(16) __half g_h2h[(NN + 1) * 32];
__device__ __align__(16) float  g_als2[NN + 1];
__device__ __align__(16) float  g_ald2[NN];
__device__ __align__(16) int    g_cnt[NN];
__device__ __align__(16) int    g_rowptr[NN + 4];
__device__ __align__(16) int    g_pos[NN];
__device__ __align__(16) int    g_csr[ET_PAD];
__device__ __align__(16) float  g_pool[GG * 32];
__device__ __align__(16) __half g_w1t[128 * 64];   // W1^T fp16: [col][k]
__device__ __align__(16) __half g_w2t[32 * 128];   // W2^T fp16: [col][k]

__device__ __forceinline__ float eluf(float v) {
    return (v > 0.f) ? v : (__expf(v) - 1.f);
}
__device__ __forceinline__ unsigned int packh2(float2 v) {
    __half2 h = __floats2half2_rn(v.x, v.y);
    return *(unsigned int*)&h;
}
__device__ __forceinline__ void mma16816(float* c,
                                         unsigned a0, unsigned a1, unsigned a2, unsigned a3,
                                         unsigned b0, unsigned b1) {
    asm volatile("mma.sync.aligned.m16n8k16.row.col.f32.f16.f16.f32 "
                 "{%0,%1,%2,%3}, {%4,%5,%6,%7}, {%8,%9}, {%0,%1,%2,%3};"
                 : "+f"(c[0]), "+f"(c[1]), "+f"(c[2]), "+f"(c[3])
                 : "r"(a0), "r"(a1), "r"(a2), "r"(a3), "r"(b0), "r"(b1));
}
__device__ __forceinline__ __half2 h2shfl_xor(__half2 v, int off) {
    unsigned u = __shfl_xor_sync(FULL, *(unsigned*)&v, off);
    return *(__half2*)&u;
}
// f is (logit sum) pre-scaled by log2e; returns exp(lrelu(e)); 0 for f = -inf
__device__ __forceinline__ float wexp2(float f) {
    float m = fmaxf(f, 0.2f * f);
    float r;
    asm("ex2.approx.f32 %0, %1;" : "=f"(r) : "f"(m));
    return r;
}

// ---------------- launch 0: histogram of dst + prefill padded CSR with dummy NN ----------------
__global__ void k_hist(const int* __restrict__ ei) {
    int t = blockIdx.x * blockDim.x + threadIdx.x;   // grid covers ET_PAD/4 = 512000
    ((int4*)g_csr)[t] = make_int4(NN, NN, NN, NN);
    if (t < EE / 4) {
        int4 d4 = ((const int4*)(ei + EE))[t];
        atomicAdd(&g_cnt[d4.x], 1);
        atomicAdd(&g_cnt[d4.y], 1);
        atomicAdd(&g_cnt[d4.z], 1);
        atomicAdd(&g_cnt[d4.w], 1);
    }
}

// ---------------- launch 1: padded prefix scan; resets g_cnt; W1T/W2T fp16; -inf pad logits ----------------
__global__ void k_scan(const float* __restrict__ W1, const float* __restrict__ W2) {
    __shared__ int sp[1024];
    int t = threadIdx.x;
#pragma unroll
    for (int i = 0; i < 8; i++) {
        int idx = t * 8 + i;                  // 0..8191
        int n = idx >> 6, k = idx & 63;
        g_w1t[idx] = __float2half(W1[k * 128 + n]);
    }
    if (t < 512) {
#pragma unroll
        for (int i = 0; i < 8; i++) {
            int idx = t * 8 + i;              // 0..4095
            int col = idx >> 7, k = idx & 127;
            g_w2t[idx] = __float2half(W2[k * 32 + col]);
        }
    }
    if (t == 0) {
        g_als1[4 * NN]     = NEG_INF;
        g_als1[4 * NN + 1] = NEG_INF;
        g_als1[4 * NN + 2] = NEG_INF;
        g_als1[4 * NN + 3] = NEG_INF;
        g_als2[NN] = NEG_INF;
    }
    int4* cv = (int4*)(g_cnt + t * 100);
    int s = 0;
#pragma unroll
    for (int i = 0; i < 25; i++) {
        int4 c = cv[i];
        s += ((c.x + 4) & ~3) + ((c.y + 4) & ~3) + ((c.z + 4) & ~3) + ((c.w + 4) & ~3);
    }
    sp[t] = s;
    __syncthreads();
    for (int off = 1; off < 1024; off <<= 1) {
        int v = (t >= off) ? sp[t - off] : 0;
        __syncthreads();
        sp[t] += v;
        __syncthreads();
    }
    int run = t ? sp[t - 1] : 0;
    int4* rp = (int4*)(g_rowptr + t * 100);
    int4* pp = (int4*)(g_pos + t * 100);
    int4 zero = make_int4(0, 0, 0, 0);
#pragma unroll
    for (int i = 0; i < 25; i++) {
        int4 c = cv[i];
        int4 r;
        r.x = run; run += (c.x + 4) & ~3;
        r.y = run; run += (c.y + 4) & ~3;
        r.z = run; run += (c.z + 4) & ~3;
        r.w = run; run += (c.w + 4) & ~3;
        rp[i] = r;
        pp[i] = r;
        cv[i] = zero;
    }
    if (t == 1023) g_rowptr[NN] = run;
}

// ---------------- launch 2: tensor-core gemm1: h1 = x @ W1 (fp16) + scaled logits ----------------
// block = 128 thr = 4 warps; warp w = head w; block covers 16 nodes x 128 cols.
__global__ void __launch_bounds__(128) k_gemm1(
        const float* __restrict__ x,
        const float* __restrict__ a_src1,
        const float* __restrict__ a_dst1) {
    int n0 = blockIdx.x * 16;
    int w = threadIdx.x >> 5;
    int l = threadIdx.x & 31;
    int g = l >> 2, tg = l & 3;

    const float2* xg  = (const float2*)(x + (n0 + g) * 64);
    const float2* xg8 = (const float2*)(x + (n0 + g + 8) * 64);

    float acc[4][4];
#pragma unroll
    for (int t = 0; t < 4; t++)
#pragma unroll
        for (int i = 0; i < 4; i++) acc[t][i] = 0.f;

#pragma unroll
    for (int ks = 0; ks < 4; ks++) {
        unsigned a0 = packh2(xg [8 * ks + tg]);
        unsigned a1 = packh2(xg8[8 * ks + tg]);
        unsigned a2 = packh2(xg [8 * ks + tg + 4]);
        unsigned a3 = packh2(xg8[8 * ks + tg + 4]);
#pragma unroll
        for (int t = 0; t < 4; t++) {
            int col = 32 * w + 8 * t + g;
            unsigned b0 = *(const unsigned*)&g_w1t[col * 64 + 16 * ks + 2 * tg];
            unsigned b1 = *(const unsigned*)&g_w1t[col * 64 + 16 * ks + 2 * tg + 8];
            mma16816(acc[t], a0, a1, a2, a3, b0, b1);
        }
    }

    float psg = 0.f, psg8 = 0.f, pdg = 0.f, pdg8 = 0.f;
#pragma unroll
    for (int t = 0; t < 4; t++) {
        int c0 = 32 * w + 8 * t + 2 * tg;
        __half2 h01 = __floats2half2_rn(acc[t][0], acc[t][1]);
        __half2 h23 = __floats2half2_rn(acc[t][2], acc[t][3]);
        *(__half2*)&g_h1h[(n0 + g) * 128 + c0]     = h01;
        *(__half2*)&g_h1h[(n0 + g + 8) * 128 + c0] = h23;
        float as0 = a_src1[c0], as1 = a_src1[c0 + 1];
        float ad0 = a_dst1[c0], ad1 = a_dst1[c0 + 1];
        psg  += acc[t][0] * as0 + acc[t][1] * as1;
        psg8 += acc[t][2] * as0 + acc[t][3] * as1;
        pdg  += acc[t][0] * ad0 + acc[t][1] * ad1;
        pdg8 += acc[t][2] * ad0 + acc[t][3] * ad1;
    }
    psg  += __shfl_down_sync(FULL, psg, 2, 4);  psg  += __shfl_down_sync(FULL, psg, 1, 4);
    psg8 += __shfl_down_sync(FULL, psg8, 2, 4); psg8 += __shfl_down_sync(FULL, psg8, 1, 4);
    pdg  += __shfl_down_sync(FULL, pdg, 2, 4);  pdg  += __shfl_down_sync(FULL, pdg, 1, 4);
    pdg8 += __shfl_down_sync(FULL, pdg8, 2, 4); pdg8 += __shfl_down_sync(FULL, pdg8, 1, 4);
    if (tg == 0) {
        g_als1[(n0 + g) * 4 + w]     = psg * LOG2E;
        g_als1[(n0 + g + 8) * 4 + w] = psg8 * LOG2E;
        g_ald1[(n0 + g) * 4 + w]     = pdg * LOG2E;
        g_ald1[(n0 + g + 8) * 4 + w] = pdg8 * LOG2E;
    }
}

// ---------------- launch 3 (PROFILED): scatter CSR ----------------
__global__ void __launch_bounds__(256) k_scatter(const int* __restrict__ ei) {
    int t = blockIdx.x * 256 + threadIdx.x;        // < 512000 = EE/4 + NN
    const int Q = EE / 4;
    if (t < Q) {
        int4 s4 = ((const int4*)ei)[t];
        int4 d4 = ((const int4*)(ei + EE))[t];
        int p;
        p = atomicAdd(&g_pos[d4.x], 1); g_csr[p] = s4.x;
        p = atomicAdd(&g_pos[d4.y], 1); g_csr[p] = s4.y;
        p = atomicAdd(&g_pos[d4.z], 1); g_csr[p] = s4.z;
        p = atomicAdd(&g_pos[d4.w], 1); g_csr[p] = s4.w;
    } else {
        int n = t - Q;
        int p = atomicAdd(&g_pos[n], 1);
        g_csr[p] = n;
    }
}

// ---------------- launch 4: gather1, branchless padded batches of 4 ----------------
__global__ void __launch_bounds__(256) k_edge1(const float* __restrict__ b1) {
    int tid = threadIdx.x;
    int lane = tid & 31;
    int d = (blockIdx.x << 3) + (tid >> 5);
    int head = lane >> 3;

    const float2* h1v = (const float2*)g_h1h;

    float ald = g_ald1[4 * d + head];
    int beg = g_rowptr[d], end = g_rowptr[d + 1];
    __half2 a01 = __float2half2_rn(0.f);
    __half2 a23 = __float2half2_rn(0.f);
    float den = 0.f;

    for (int j = beg; j < end; j += 4) {
        int4 s4 = *(const int4*)&g_csr[j];
        float l0 = g_als1[4 * s4.x + head];
        float l1 = g_als1[4 * s4.y + head];
        float l2 = g_als1[4 * s4.z + head];
        float l3 = g_als1[4 * s4.w + head];
        float2 r0 = h1v[(s4.x << 5) + lane];
        float2 r1 = h1v[(s4.y << 5) + lane];
        float2 r2 = h1v[(s4.z << 5) + lane];
        float2 r3 = h1v[(s4.w << 5) + lane];
        float w0 = wexp2(l0 + ald);
        float w1 = wexp2(l1 + ald);
        float w2 = wexp2(l2 + ald);
        float w3 = wexp2(l3 + ald);
        den += (w0 + w1) + (w2 + w3);
        __half2 h0 = __float2half2_rn(w0);
        __half2 h1w = __float2half2_rn(w1);
        __half2 h2w = __float2half2_rn(w2);
        __half2 h3w = __float2half2_rn(w3);
        a01 = __hfma2(*(__half2*)&r0.x, h0, a01);
        a23 = __hfma2(*(__half2*)&r0.y, h0, a23);
        a01 = __hfma2(*(__half2*)&r1.x, h1w, a01);
        a23 = __hfma2(*(__half2*)&r1.y, h1w, a23);
        a01 = __hfma2(*(__half2*)&r2.x, h2w, a01);
        a23 = __hfma2(*(__half2*)&r2.y, h2w, a23);
        a01 = __hfma2(*(__half2*)&r3.x, h3w, a01);
        a23 = __hfma2(*(__half2*)&r3.y, h3w, a23);
    }

    float inv = 1.f / den;
    float4 bb = *(const float4*)&b1[lane * 4];
    float2 f01 = __half22float2(a01);
    float2 f23 = __half22float2(a23);
    __half2 p0 = __floats2half2_rn(eluf(f01.x * inv + bb.x), eluf(f01.y * inv + bb.y));
    __half2 p1 = __floats2half2_rn(eluf(f23.x * inv + bb.z), eluf(f23.y * inv + bb.w));
    uint2 st;
    st.x = *(unsigned int*)&p0;
    st.y = *(unsigned int*)&p1;
    ((uint2*)g_act)[(d << 5) + lane] = st;
}

// ---------------- launch 5: tensor-core gemm2: h2 = act @ W2 (fp16) + scaled logits2 ----------------
// block = 128 thr = 4 warps; warp covers 16 nodes x 32 cols; block = 64 nodes.
__global__ void __launch_bounds__(128) k_gemm2(const float* __restrict__ a2s,
                                               const float* __restrict__ a2d) {
    int w = threadIdx.x >> 5;
    int l = threadIdx.x & 31;
    int g = l >> 2, tg = l & 3;
    int n0 = blockIdx.x * 64 + w * 16;

    const __half* act0 = &g_act[(n0 + g) * 128];
    const __half* act8 = &g_act[(n0 + g + 8) * 128];

    float acc[4][4];
#pragma unroll
    for (int t = 0; t < 4; t++)
#pragma unroll
        for (int i = 0; i < 4; i++) acc[t][i] = 0.f;

#pragma unroll
    for (int ks = 0; ks < 8; ks++) {
        unsigned a0 = *(const unsigned*)&act0[16 * ks + 2 * tg];
        unsigned a1 = *(const unsigned*)&act8[16 * ks + 2 * tg];
        unsigned a2 = *(const unsigned*)&act0[16 * ks + 8 + 2 * tg];
        unsigned a3 = *(const unsigned*)&act8[16 * ks + 8 + 2 * tg];
#pragma unroll
        for (int t = 0; t < 4; t++) {
            int col = 8 * t + g;
            unsigned b0 = *(const unsigned*)&g_w2t[col * 128 + 16 * ks + 2 * tg];
            unsigned b1 = *(const unsigned*)&g_w2t[col * 128 + 16 * ks + 2 * tg + 8];
            mma16816(acc[t], a0, a1, a2, a3, b0, b1);
        }
    }

    float psg = 0.f, psg8 = 0.f, pdg = 0.f, pdg8 = 0.f;
#pragma unroll
    for (int t = 0; t < 4; t++) {
        int c0 = 8 * t + 2 * tg;
        __half2 h01 = __floats2half2_rn(acc[t][0], acc[t][1]);
        __half2 h23 = __floats2half2_rn(acc[t][2], acc[t][3]);
        *(__half2*)&g_h2h[(n0 + g) * 32 + c0]     = h01;
        *(__half2*)&g_h2h[(n0 + g + 8) * 32 + c0] = h23;
        float as0 = a2s[c0], as1 = a2s[c0 + 1];
        float ad0 = a2d[c0], ad1 = a2d[c0 + 1];
        psg  += acc[t][0] * as0 + acc[t][1] * as1;
        psg8 += acc[t][2] * as0 + acc[t][3] * as1;
        pdg  += acc[t][0] * ad0 + acc[t][1] * ad1;
        pdg8 += acc[t][2] * ad0 + acc[t][3] * ad1;
    }
    psg  += __shfl_down_sync(FULL, psg, 2, 4);  psg  += __shfl_down_sync(FULL, psg, 1, 4);
    psg8 += __shfl_down_sync(FULL, psg8, 2, 4); psg8 += __shfl_down_sync(FULL, psg8, 1, 4);
    pdg  += __shfl_down_sync(FULL, pdg, 2, 4);  pdg  += __shfl_down_sync(FULL, pdg, 1, 4);
    pdg8 += __shfl_down_sync(FULL, pdg8, 2, 4); pdg8 += __shfl_down_sync(FULL, pdg8, 1, 4);
    if (tg == 0) {
        g_als2[n0 + g]      = psg * LOG2E;
        g_als2[n0 + g + 8]  = psg8 * LOG2E;
        g_ald2[n0 + g]      = pdg * LOG2E;
        g_ald2[n0 + g + 8]  = pdg8 * LOG2E;
    }
}

// ---------------- launch 6: gather2, branchless padded; pooled reduction ----------------
__global__ void __launch_bounds__(256) k_edge2(const float* __restrict__ b2) {
    int lane = threadIdx.x & 31;
    int d = (blockIdx.x << 3) + (threadIdx.x >> 5);
    int hw = lane >> 4;
    int c2 = (lane & 15) << 1;
    float ald = g_ald2[d];
    int beg = g_rowptr[d], end = g_rowptr[d + 1];
    __half2 acc = __float2half2_rn(0.f);
    float den = 0.f;
    for (int j = beg; j < end; j += 4) {
        int s0 = g_csr[j + hw];
        int s1 = g_csr[j + 2 + hw];
        float l0 = g_als2[s0];
        float l1 = g_als2[s1];
        __half2 v0 = *(const __half2*)(g_h2h + s0 * 32 + c2);
        __half2 v1 = *(const __half2*)(g_h2h + s1 * 32 + c2);
        float w0 = wexp2(l0 + ald);
        float w1 = wexp2(l1 + ald);
        den += w0 + w1;
        acc = __hfma2(v0, __float2half2_rn(w0), acc);
        acc = __hfma2(v1, __float2half2_rn(w1), acc);
    }
    den += __shfl_xor_sync(FULL, den, 16);
    acc = __hadd2(acc, h2shfl_xor(acc, 16));
    if (hw == 0) {
        float inv = 1.f / den;
        float2 f = __half22float2(acc);
        float vx = eluf(f.x * inv + b2[c2]);
        float vy = eluf(f.y * inv + b2[c2 + 1]);
        int g = d / 400;
        atomicAdd(&g_pool[g * 32 + c2], vx);
        atomicAdd(&g_pool[g * 32 + c2 + 1], vy);
    }
}

// ---------------- launch 7: classifier MLP (resets g_pool) ----------------
__global__ void k_mlp(const float* __restrict__ clinical,
                      const float* __restrict__ Wc1,
                      const float* __restrict__ bc1,
                      const float* __restrict__ Wc2,
                      const float* __restrict__ bc2,
                      float* __restrict__ out) {
    int g = blockIdx.x;
    int t = threadIdx.x;
    __shared__ float sf[37];
    __shared__ float sz[16];
    if (t < 32) {
        sf[t] = g_pool[g * 32 + t] * (1.f / 400.f);
        g_pool[g * 32 + t] = 0.f;
    } else if (t < 37) {
        sf[t] = clinical[g * 5 + (t - 32)];
    }
    __syncthreads();
    if (t < 16) {
        float z = bc1[t];
#pragma unroll
        for (int i = 0; i < 37; i++) z += sf[i] * Wc1[i * 16 + t];
        sz[t] = eluf(z);
    }
    __syncthreads();
    if (t == 0) {
        float o = bc2[0];
#pragma unroll
        for (int j = 0; j < 16; j++) o += sz[j] * Wc2[j];
        out[g] = o;
    }
}

// ---------------- launch ----------------
extern "C" void kernel_launch(void* const* d_in, const int* in_sizes, int n_in,
                              void* d_out, int out_size) {
    const float* x        = (const float*)d_in[0];
    const int*   ei       = (const int*)d_in[1];
    const float* clinical = (const float*)d_in[3];
    const float* W1       = (const float*)d_in[4];
    const float* a_src1   = (const float*)d_in[5];
    const float* a_dst1   = (const float*)d_in[6];
    const float* b1       = (const float*)d_in[7];
    const float* W2       = (const float*)d_in[8];
    const float* a_src2   = (const float*)d_in[9];
    const float* a_dst2   = (const float*)d_in[10];
    const float* b2       = (const float*)d_in[11];
    const float* Wc1      = (const float*)d_in[12];
    const float* bc1      = (const float*)d_in[13];
    const float* Wc2      = (const float*)d_in[14];
    const float* bc2      = (const float*)d_in[15];
    float* out = (float*)d_out;

    k_hist<<<ET_PAD / 4 / 256, 256>>>(ei);
    k_scan<<<1, 1024>>>(W1, W2);
    k_gemm1<<<NN / 16, 128>>>(x, a_src1, a_dst1);
    k_scatter<<<(EE / 4 + NN) / 256, 256>>>(ei);        // idx 3 -> profiled
    k_edge1<<<NN / 8, 256>>>(b1);
    k_gemm2<<<NN / 64, 128>>>(a_src2, a_dst2);
    k_edge2<<<NN / 8, 256>>>(b2);
    k_mlp<<<GG, 64>>>(clinical, Wc1, bc1, Wc2, bc2, out);
}

// round 14
// speedup vs baseline: 2.1381x; 1.3261x over previous
#include <cuda_runtime.h>
#include <cuda_fp16.h>

#define NN 102400
#define EE 1638400
#define SLOTS 64                  // fixed CSR row capacity (P(overflow) ~ 1e-20)
#define GG 256
#define FULL 0xffffffffu
#define NEG_INF __int_as_float(0xff800000)
#define LOG2E 1.4426950408889634f

// ---------------- scratch (device globals; no allocation) ----------------
// Invariant: g_pos and g_pool are ZERO at entry of every kernel_launch call.
// Rows NN of g_h1h / g_h2h are NEVER written -> remain zero (dummy pad node).
// All logits are stored PRE-SCALED by log2(e).
__device__ __align__(16) __half g_h1h[(NN + 1) * 128];
__device__ __align__(16) float  g_als1[(NN + 1) * 4];
__device__ __align__(16) float  g_ald1[NN * 4];
__device__ __align__(16) __half g_act[NN * 128];
__device__ __align__(16) __half g_h2h[(NN + 1) * 32];
__device__ __align__(16) float  g_als2[NN + 1];
__device__ __align__(16) float  g_ald2[NN];
__device__ __align__(16) int    g_pos[NN];
__device__ __align__(16) int    g_len[NN];
__device__ __align__(16) int    g_csr[NN * SLOTS];
__device__ __align__(16) float  g_pool[GG * 32];
__device__ __align__(16) __half g_w1t[128 * 64];   // W1^T fp16: [col][k]
__device__ __align__(16) __half g_w2t[32 * 128];   // W2^T fp16: [col][k]

__device__ __forceinline__ float eluf(float v) {
    return (v > 0.f) ? v : (__expf(v) - 1.f);
}
__device__ __forceinline__ unsigned int packh2(float2 v) {
    __half2 h = __floats2half2_rn(v.x, v.y);
    return *(unsigned int*)&h;
}
__device__ __forceinline__ void mma16816(float* c,
                                         unsigned a0, unsigned a1, unsigned a2, unsigned a3,
                                         unsigned b0, unsigned b1) {
    asm volatile("mma.sync.aligned.m16n8k16.row.col.f32.f16.f16.f32 "
                 "{%0,%1,%2,%3}, {%4,%5,%6,%7}, {%8,%9}, {%0,%1,%2,%3};"
                 : "+f"(c[0]), "+f"(c[1]), "+f"(c[2]), "+f"(c[3])
                 : "r"(a0), "r"(a1), "r"(a2), "r"(a3), "r"(b0), "r"(b1));
}
__device__ __forceinline__ __half2 h2shfl_xor(__half2 v, int off) {
    unsigned u = __shfl_xor_sync(FULL, *(unsigned*)&v, off);
    return *(__half2*)&u;
}
// f is (logit sum) pre-scaled by log2e; returns exp(lrelu(e)); 0 for f = -inf
__device__ __forceinline__ float wexp2(float f) {
    float m = fmaxf(f, 0.2f * f);
    float r;
    asm("ex2.approx.f32 %0, %1;" : "=f"(r) : "f"(m));
    return r;
}

// ---------------- launch 0: bucket scatter (no hist/scan) + W1T/W2T conversion ----------------
#define SCAT_BLOCKS 2000           // (EE/4 + NN) / 256
__global__ void __launch_bounds__(256) k_scatter(
        const int* __restrict__ ei,
        const float* __restrict__ W1,
        const float* __restrict__ W2) {
    int b = blockIdx.x;
    if (b < SCAT_BLOCKS) {
        int t = b * 256 + threadIdx.x;         // < 512000 = EE/4 + NN
        const int Q = EE / 4;
        if (t < Q) {
            int4 s4 = ((const int4*)ei)[t];
            int4 d4 = ((const int4*)(ei + EE))[t];
            int p;
            p = atomicAdd(&g_pos[d4.x], 1); g_csr[(d4.x << 6) + p] = s4.x;
            p = atomicAdd(&g_pos[d4.y], 1); g_csr[(d4.y << 6) + p] = s4.y;
            p = atomicAdd(&g_pos[d4.z], 1); g_csr[(d4.z << 6) + p] = s4.z;
            p = atomicAdd(&g_pos[d4.w], 1); g_csr[(d4.w << 6) + p] = s4.w;
        } else {
            int n = t - Q;                      // self loop
            int p = atomicAdd(&g_pos[n], 1);
            g_csr[(n << 6) + p] = n;
        }
        return;
    }
    int idx = (b - SCAT_BLOCKS) * 256 + threadIdx.x;   // 0..12287
    if (idx < 8192) {
        int n = idx >> 6, k = idx & 63;
        g_w1t[idx] = __float2half(W1[k * 128 + n]);
    } else {
        int j = idx - 8192;                    // 0..4095
        int col = j >> 7, k = j & 127;
        g_w2t[j] = __float2half(W2[k * 32 + col]);
    }
    if (idx == 0) {
        g_als1[4 * NN]     = NEG_INF;
        g_als1[4 * NN + 1] = NEG_INF;
        g_als1[4 * NN + 2] = NEG_INF;
        g_als1[4 * NN + 3] = NEG_INF;
        g_als2[NN] = NEG_INF;
    }
}

// ---------------- launch 1: pad rows to multiple of 4; store len; reset g_pos ----------------
__global__ void k_pad() {
    int n = blockIdx.x * blockDim.x + threadIdx.x;
    if (n >= NN) return;
    int p = g_pos[n];
    g_pos[n] = 0;                              // restore invariant
    int end = (p + 3) & ~3;
    g_len[n] = end;
    int base = n << 6;
    for (int i = p; i < end; i++) g_csr[base + i] = NN;
}

// ---------------- launch 2: tensor-core gemm1: h1 = x @ W1 (fp16) + scaled logits ----------------
__global__ void __launch_bounds__(128) k_gemm1(
        const float* __restrict__ x,
        const float* __restrict__ a_src1,
        const float* __restrict__ a_dst1) {
    int n0 = blockIdx.x * 16;
    int w = threadIdx.x >> 5;
    int l = threadIdx.x & 31;
    int g = l >> 2, tg = l & 3;

    const float2* xg  = (const float2*)(x + (n0 + g) * 64);
    const float2* xg8 = (const float2*)(x + (n0 + g + 8) * 64);

    float acc[4][4];
#pragma unroll
    for (int t = 0; t < 4; t++)
#pragma unroll
        for (int i = 0; i < 4; i++) acc[t][i] = 0.f;

#pragma unroll
    for (int ks = 0; ks < 4; ks++) {
        unsigned a0 = packh2(xg [8 * ks + tg]);
        unsigned a1 = packh2(xg8[8 * ks + tg]);
        unsigned a2 = packh2(xg [8 * ks + tg + 4]);
        unsigned a3 = packh2(xg8[8 * ks + tg + 4]);
#pragma unroll
        for (int t = 0; t < 4; t++) {
            int col = 32 * w + 8 * t + g;
            unsigned b0 = *(const unsigned*)&g_w1t[col * 64 + 16 * ks + 2 * tg];
            unsigned b1 = *(const unsigned*)&g_w1t[col * 64 + 16 * ks + 2 * tg + 8];
            mma16816(acc[t], a0, a1, a2, a3, b0, b1);
        }
    }

    float psg = 0.f, psg8 = 0.f, pdg = 0.f, pdg8 = 0.f;
#pragma unroll
    for (int t = 0; t < 4; t++) {
        int c0 = 32 * w + 8 * t + 2 * tg;
        __half2 h01 = __floats2half2_rn(acc[t][0], acc[t][1]);
        __half2 h23 = __floats2half2_rn(acc[t][2], acc[t][3]);
        *(__half2*)&g_h1h[(n0 + g) * 128 + c0]     = h01;
        *(__half2*)&g_h1h[(n0 + g + 8) * 128 + c0] = h23;
        float as0 = a_src1[c0], as1 = a_src1[c0 + 1];
        float ad0 = a_dst1[c0], ad1 = a_dst1[c0 + 1];
        psg  += acc[t][0] * as0 + acc[t][1] * as1;
        psg8 += acc[t][2] * as0 + acc[t][3] * as1;
        pdg  += acc[t][0] * ad0 + acc[t][1] * ad1;
        pdg8 += acc[t][2] * ad0 + acc[t][3] * ad1;
    }
    psg  += __shfl_down_sync(FULL, psg, 2, 4);  psg  += __shfl_down_sync(FULL, psg, 1, 4);
    psg8 += __shfl_down_sync(FULL, psg8, 2, 4); psg8 += __shfl_down_sync(FULL, psg8, 1, 4);
    pdg  += __shfl_down_sync(FULL, pdg, 2, 4);  pdg  += __shfl_down_sync(FULL, pdg, 1, 4);
    pdg8 += __shfl_down_sync(FULL, pdg8, 2, 4); pdg8 += __shfl_down_sync(FULL, pdg8, 1, 4);
    if (tg == 0) {
        g_als1[(n0 + g) * 4 + w]     = psg * LOG2E;
        g_als1[(n0 + g + 8) * 4 + w] = psg8 * LOG2E;
        g_ald1[(n0 + g) * 4 + w]     = pdg * LOG2E;
        g_ald1[(n0 + g + 8) * 4 + w] = pdg8 * LOG2E;
    }
}

// ---------------- launch 3 (PROFILED): gather1, branchless padded batches of 4 ----------------
__global__ void __launch_bounds__(256) k_edge1(const float* __restrict__ b1) {
    int tid = threadIdx.x;
    int lane = tid & 31;
    int d = (blockIdx.x << 3) + (tid >> 5);
    int head = lane >> 3;

    const float2* h1v = (const float2*)g_h1h;

    float ald = g_ald1[4 * d + head];
    int beg = d << 6, end = beg + g_len[d];
    __half2 a01 = __float2half2_rn(0.f);
    __half2 a23 = __float2half2_rn(0.f);
    float den = 0.f;

    for (int j = beg; j < end; j += 4) {
        int4 s4 = *(const int4*)&g_csr[j];
        float l0 = g_als1[4 * s4.x + head];
        float l1 = g_als1[4 * s4.y + head];
        float l2 = g_als1[4 * s4.z + head];
        float l3 = g_als1[4 * s4.w + head];
        float2 r0 = h1v[(s4.x << 5) + lane];
        float2 r1 = h1v[(s4.y << 5) + lane];
        float2 r2 = h1v[(s4.z << 5) + lane];
        float2 r3 = h1v[(s4.w << 5) + lane];
        float w0 = wexp2(l0 + ald);
        float w1 = wexp2(l1 + ald);
        float w2 = wexp2(l2 + ald);
        float w3 = wexp2(l3 + ald);
        den += (w0 + w1) + (w2 + w3);
        __half2 h0 = __float2half2_rn(w0);
        __half2 h1w = __float2half2_rn(w1);
        __half2 h2w = __float2half2_rn(w2);
        __half2 h3w = __float2half2_rn(w3);
        a01 = __hfma2(*(__half2*)&r0.x, h0, a01);
        a23 = __hfma2(*(__half2*)&r0.y, h0, a23);
        a01 = __hfma2(*(__half2*)&r1.x, h1w, a01);
        a23 = __hfma2(*(__half2*)&r1.y, h1w, a23);
        a01 = __hfma2(*(__half2*)&r2.x, h2w, a01);
        a23 = __hfma2(*(__half2*)&r2.y, h2w, a23);
        a01 = __hfma2(*(__half2*)&r3.x, h3w, a01);
        a23 = __hfma2(*(__half2*)&r3.y, h3w, a23);
    }

    float inv = 1.f / den;
    float4 bb = *(const float4*)&b1[lane * 4];
    float2 f01 = __half22float2(a01);
    float2 f23 = __half22float2(a23);
    __half2 p0 = __floats2half2_rn(eluf(f01.x * inv + bb.x), eluf(f01.y * inv + bb.y));
    __half2 p1 = __floats2half2_rn(eluf(f23.x * inv + bb.z), eluf(f23.y * inv + bb.w));
    uint2 st;
    st.x = *(unsigned int*)&p0;
    st.y = *(unsigned int*)&p1;
    ((uint2*)g_act)[(d << 5) + lane] = st;
}

// ---------------- launch 4: tensor-core gemm2: h2 = act @ W2 (fp16) + scaled logits2 ----------------
__global__ void __launch_bounds__(128) k_gemm2(const float* __restrict__ a2s,
                                               const float* __restrict__ a2d) {
    int w = threadIdx.x >> 5;
    int l = threadIdx.x & 31;
    int g = l >> 2, tg = l & 3;
    int n0 = blockIdx.x * 64 + w * 16;

    const __half* act0 = &g_act[(n0 + g) * 128];
    const __half* act8 = &g_act[(n0 + g + 8) * 128];

    float acc[4][4];
#pragma unroll
    for (int t = 0; t < 4; t++)
#pragma unroll
        for (int i = 0; i < 4; i++) acc[t][i] = 0.f;

#pragma unroll
    for (int ks = 0; ks < 8; ks++) {
        unsigned a0 = *(const unsigned*)&act0[16 * ks + 2 * tg];
        unsigned a1 = *(const unsigned*)&act8[16 * ks + 2 * tg];
        unsigned a2 = *(const unsigned*)&act0[16 * ks + 8 + 2 * tg];
        unsigned a3 = *(const unsigned*)&act8[16 * ks + 8 + 2 * tg];
#pragma unroll
        for (int t = 0; t < 4; t++) {
            int col = 8 * t + g;
            unsigned b0 = *(const unsigned*)&g_w2t[col * 128 + 16 * ks + 2 * tg];
            unsigned b1 = *(const unsigned*)&g_w2t[col * 128 + 16 * ks + 2 * tg + 8];
            mma16816(acc[t], a0, a1, a2, a3, b0, b1);
        }
    }

    float psg = 0.f, psg8 = 0.f, pdg = 0.f, pdg8 = 0.f;
#pragma unroll
    for (int t = 0; t < 4; t++) {
        int c0 = 8 * t + 2 * tg;
        __half2 h01 = __floats2half2_rn(acc[t][0], acc[t][1]);
        __half2 h23 = __floats2half2_rn(acc[t][2], acc[t][3]);
        *(__half2*)&g_h2h[(n0 + g) * 32 + c0]     = h01;
        *(__half2*)&g_h2h[(n0 + g + 8) * 32 + c0] = h23;
        float as0 = a2s[c0], as1 = a2s[c0 + 1];
        float ad0 = a2d[c0], ad1 = a2d[c0 + 1];
        psg  += acc[t][0] * as0 + acc[t][1] * as1;
        psg8 += acc[t][2] * as0 + acc[t][3] * as1;
        pdg  += acc[t][0] * ad0 + acc[t][1] * ad1;
        pdg8 += acc[t][2] * ad0 + acc[t][3] * ad1;
    }
    psg  += __shfl_down_sync(FULL, psg, 2, 4);  psg  += __shfl_down_sync(FULL, psg, 1, 4);
    psg8 += __shfl_down_sync(FULL, psg8, 2, 4); psg8 += __shfl_down_sync(FULL, psg8, 1, 4);
    pdg  += __shfl_down_sync(FULL, pdg, 2, 4);  pdg  += __shfl_down_sync(FULL, pdg, 1, 4);
    pdg8 += __shfl_down_sync(FULL, pdg8, 2, 4); pdg8 += __shfl_down_sync(FULL, pdg8, 1, 4);
    if (tg == 0) {
        g_als2[n0 + g]      = psg * LOG2E;
        g_als2[n0 + g + 8]  = psg8 * LOG2E;
        g_ald2[n0 + g]      = pdg * LOG2E;
        g_ald2[n0 + g + 8]  = pdg8 * LOG2E;
    }
}

// ---------------- launch 5: gather2, branchless padded; pooled reduction ----------------
__global__ void __launch_bounds__(256) k_edge2(const float* __restrict__ b2) {
    int lane = threadIdx.x & 31;
    int d = (blockIdx.x << 3) + (threadIdx.x >> 5);
    int hw = lane >> 4;
    int c2 = (lane & 15) << 1;
    float ald = g_ald2[d];
    int beg = d << 6, end = beg + g_len[d];
    __half2 acc = __float2half2_rn(0.f);
    float den = 0.f;
    for (int j = beg; j < end; j += 4) {
        int s0 = g_csr[j + hw];
        int s1 = g_csr[j + 2 + hw];
        float l0 = g_als2[s0];
        float l1 = g_als2[s1];
        __half2 v0 = *(const __half2*)(g_h2h + s0 * 32 + c2);
        __half2 v1 = *(const __half2*)(g_h2h + s1 * 32 + c2);
        float w0 = wexp2(l0 + ald);
        float w1 = wexp2(l1 + ald);
        den += w0 + w1;
        acc = __hfma2(v0, __float2half2_rn(w0), acc);
        acc = __hfma2(v1, __float2half2_rn(w1), acc);
    }
    den += __shfl_xor_sync(FULL, den, 16);
    acc = __hadd2(acc, h2shfl_xor(acc, 16));
    if (hw == 0) {
        float inv = 1.f / den;
        float2 f = __half22float2(acc);
        float vx = eluf(f.x * inv + b2[c2]);
        float vy = eluf(f.y * inv + b2[c2 + 1]);
        int g = d / 400;
        atomicAdd(&g_pool[g * 32 + c2], vx);
        atomicAdd(&g_pool[g * 32 + c2 + 1], vy);
    }
}

// ---------------- launch 6: classifier MLP (resets g_pool) ----------------
__global__ void k_mlp(const float* __restrict__ clinical,
                      const float* __restrict__ Wc1,
                      const float* __restrict__ bc1,
                      const float* __restrict__ Wc2,
                      const float* __restrict__ bc2,
                      float* __restrict__ out) {
    int g = blockIdx.x;
    int t = threadIdx.x;
    __shared__ float sf[37];
    __shared__ float sz[16];
    if (t < 32) {
        sf[t] = g_pool[g * 32 + t] * (1.f / 400.f);
        g_pool[g * 32 + t] = 0.f;
    } else if (t < 37) {
        sf[t] = clinical[g * 5 + (t - 32)];
    }
    __syncthreads();
    if (t < 16) {
        float z = bc1[t];
#pragma unroll
        for (int i = 0; i < 37; i++) z += sf[i] * Wc1[i * 16 + t];
        sz[t] = eluf(z);
    }
    __syncthreads();
    if (t == 0) {
        float o = bc2[0];
#pragma unroll
        for (int j = 0; j < 16; j++) o += sz[j] * Wc2[j];
        out[g] = o;
    }
}

// ---------------- launch ----------------
extern "C" void kernel_launch(void* const* d_in, const int* in_sizes, int n_in,
                              void* d_out, int out_size) {
    const float* x        = (const float*)d_in[0];
    const int*   ei       = (const int*)d_in[1];
    const float* clinical = (const float*)d_in[3];
    const float* W1       = (const float*)d_in[4];
    const float* a_src1   = (const float*)d_in[5];
    const float* a_dst1   = (const float*)d_in[6];
    const float* b1       = (const float*)d_in[7];
    const float* W2       = (const float*)d_in[8];
    const float* a_src2   = (const float*)d_in[9];
    const float* a_dst2   = (const float*)d_in[10];
    const float* b2       = (const float*)d_in[11];
    const float* Wc1      = (const float*)d_in[12];
    const float* bc1      = (const float*)d_in[13];
    const float* Wc2      = (const float*)d_in[14];
    const float* bc2      = (const float*)d_in[15];
    float* out = (float*)d_out;

    k_scatter<<<SCAT_BLOCKS + 48, 256>>>(ei, W1, W2);
    k_pad<<<(NN + 255) / 256, 256>>>();
    k_gemm1<<<NN / 16, 128>>>(x, a_src1, a_dst1);
    k_edge1<<<NN / 8, 256>>>(b1);                       // idx 3 -> profiled
    k_gemm2<<<NN / 64, 128>>>(a_src2, a_dst2);
    k_edge2<<<NN / 8, 256>>>(b2);
    k_mlp<<<GG, 64>>>(clinical, Wc1, bc1, Wc2, bc2, out);
}